// round 9
// baseline (speedup 1.0000x reference)
#include <cuda_runtime.h>
#include <math.h>
#include <stdint.h>

// ---------------- constants ----------------
static const int TSEQ = 2048;
static const int DMODEL = 1024;
static const int NHEAD = 16;
static const int HDIM = 64;
static const int DFFN = 4096;
static const int NEXP = 8;
static const int HIDX = 4;
static const int DIDX = 64;
static const int KSEL = 512;
static const int NPROJ_IDX = HIDX * DIDX + DIDX + HIDX;  // 324
static const int NPROJ_QKV = 3 * DMODEL;                 // 3072

// ---------------- device scratch ----------------
__device__ float g_xn[TSEQ * DMODEL];
__device__ float g_proj_idx[TSEQ * NPROJ_IDX];
__device__ float g_qkv[TSEQ * NPROJ_QKV];
__device__ float g_qh[TSEQ * DMODEL];
__device__ float g_kh[TSEQ * DMODEL];
__device__ float g_vh[TSEQ * DMODEL];
__device__ float g_av[TSEQ * DMODEL];
__device__ float g_x1[TSEQ * DMODEL];
__device__ float g_x2n[TSEQ * DMODEL];   // tf32-rounded (GEMM operand)
__device__ float g_x2f[TSEQ * DMODEL];   // full fp32 (router input)
__device__ float g_probs[TSEQ * NEXP];
__device__ int   g_topE[TSEQ * 2];
__device__ float g_topG[TSEQ * 2];
__device__ int   g_counts[NEXP];
__device__ int   g_segoff[NEXP + 1];
__device__ int   g_rowmap[TSEQ * 2];
__device__ int   g_slotpos[TSEQ * 2];
__device__ float g_mid[(size_t)(TSEQ * 2) * DFFN];
__device__ float g_yy[(size_t)(TSEQ * 2) * DMODEL];
__device__ unsigned int g_mask[TSEQ * (TSEQ / 32)];
// tf32-rounded weight copies (small ones only; w1/w2 are converted in-GEMM)
__device__ float g_woc[DMODEL * DMODEL];
__device__ float g_wqkvc[DMODEL * NPROJ_QKV];
__device__ float g_widxc[DMODEL * NPROJ_IDX];

// ---------------- helpers ----------------
__device__ __forceinline__ float gelu_tanh(float x) {
    float x3 = x * x * x;
    float u = 0.7978845608028654f * (x + 0.044715f * x3);
    return 0.5f * x * (1.0f + tanhf(u));
}

__device__ __forceinline__ unsigned int fmono(float f) {
    unsigned int u = __float_as_uint(f);
    return (u & 0x80000000u) ? ~u : (u | 0x80000000u);
}

__device__ __forceinline__ uint32_t f2tf32(float f) {
    uint32_t r;
    asm("cvt.rna.tf32.f32 %0, %1;" : "=r"(r) : "f"(f));
    return r;
}
__device__ __forceinline__ float rtf(float f) { return __uint_as_float(f2tf32(f)); }

__device__ __forceinline__ void cp16(uint32_t dst, const float* src, int sz) {
    asm volatile("cp.async.cg.shared.global [%0], [%1], 16, %2;" :: "r"(dst), "l"(src), "r"(sz));
}

__device__ __forceinline__ void mma_tf32(float* c, const uint32_t* a, const uint32_t* b) {
    asm volatile(
        "mma.sync.aligned.m16n8k8.row.col.f32.tf32.tf32.f32 "
        "{%0,%1,%2,%3}, {%4,%5,%6,%7}, {%8,%9}, {%0,%1,%2,%3};"
        : "+f"(c[0]), "+f"(c[1]), "+f"(c[2]), "+f"(c[3])
        : "r"(a[0]), "r"(a[1]), "r"(a[2]), "r"(a[3]), "r"(b[0]), "r"(b[1]));
}

// ---------------- weight conversion / packing (small weights only) ----------------
__global__ __launch_bounds__(256) void round4_kernel(
    const float4* __restrict__ in, float4* __restrict__ out, int n4)
{
    int i = blockIdx.x * 256 + threadIdx.x;
    if (i < n4) {
        float4 v = in[i];
        v.x = rtf(v.x); v.y = rtf(v.y); v.z = rtf(v.z); v.w = rtf(v.w);
        out[i] = v;
    }
}

__global__ __launch_bounds__(256) void pack_qkv_kernel(
    const float* __restrict__ wq, const float* __restrict__ wk, const float* __restrict__ wv,
    float* __restrict__ out)
{
    int i = blockIdx.x * 256 + threadIdx.x;  // over 1024*1024
    int d = i >> 10, c = i & 1023;
    out[(size_t)d * NPROJ_QKV + c] = rtf(wq[i]);
    out[(size_t)d * NPROJ_QKV + DMODEL + c] = rtf(wk[i]);
    out[(size_t)d * NPROJ_QKV + 2 * DMODEL + c] = rtf(wv[i]);
}

__global__ __launch_bounds__(256) void pack_idx_kernel(
    const float* __restrict__ wq_idx, const float* __restrict__ wk_idx,
    const float* __restrict__ w_head, float* __restrict__ out)
{
    int i = blockIdx.x * 256 + threadIdx.x;  // over 1024*324
    if (i >= DMODEL * NPROJ_IDX) return;
    int d = i / NPROJ_IDX, j = i - d * NPROJ_IDX;
    float v;
    if (j < 256) v = wq_idx[d * 256 + j];
    else if (j < 320) v = wk_idx[d * 64 + (j - 256)];
    else v = w_head[d * 4 + (j - 320)];
    out[i] = rtf(v);
}

// ---------------- unified tf32 tensor GEMM, templated tile height ----------------
// CVTB=1: B raw fp32, rounded at fragment load (bit-identical to pre-rounded copy).
// TBM: row-tile height (128 -> 256 thr, 3 stages, 2 CTA/SM; 256 -> 512 thr, 2 stages, 1 CTA/SM).
#define BKK 32
#define LDA_S 36
#define LDB_S 132
#define B_STAGE (BKK * LDB_S)

extern __shared__ float smem_dyn[];

template <int CVTB, int TBM>
__global__ void __launch_bounds__(TBM * 2, TBM == 128 ? 2 : 1) tgemm(
    const float* __restrict__ A, int lda,
    const int* __restrict__ rowmap,
    const float* __restrict__ Bbase, long long strideB,
    const float* __restrict__ biasBase, int biasStride,
    const float* __restrict__ residual,
    float* __restrict__ C, int ldc,
    const int* __restrict__ segoff,
    int M, int N, int K, int doGelu)
{
    constexpr int NTHR = TBM * 2;
    constexpr int NST = (TBM == 128) ? 3 : 2;
    constexpr int A_ST = TBM * LDA_S;
    constexpr int STF = A_ST + B_STAGE;
    constexpr int ACNT = 4;                 // A float4 per thread: TBM*8 / NTHR = 4
    constexpr int BCNT = 1024 / NTHR;       // B float4 per thread: 4 or 2

    int e = blockIdx.z;
    int s0 = 0, nrows = M;
    if (segoff) { s0 = segoff[e]; nrows = segoff[e + 1] - s0; }
    int rowTile = blockIdx.y;
    if (rowTile * TBM >= nrows) return;
    int colStart = blockIdx.x * 128;
    const float* B = Bbase + (long long)e * strideB;

    int tid = threadIdx.x;
    int warpId = tid >> 5, lane = tid & 31;
    int grp = lane >> 2, tig = lane & 3;
    int wm = (warpId >> 2) * 64;
    int wn = (warpId & 3) * 32;

    uint32_t sbase = (uint32_t)__cvta_generic_to_shared(smem_dyn);

    const float* aSrc[ACNT]; int aSz[ACNT]; uint32_t aDst[ACNT];
    const float* bSrc[BCNT]; int bSz[BCNT]; uint32_t bDst[BCNT];
#pragma unroll
    for (int i = 0; i < ACNT; i++) {
        int j = tid + i * NTHR;             // A float4 index in [0, TBM*8)
        int arow = j >> 3, akc = (j & 7) * 4;
        int lrow = rowTile * TBM + arow;
        bool v = lrow < nrows;
        int gidx = 0;
        if (v) {
            int base = s0 + lrow;
            gidx = rowmap ? rowmap[base] : base;
        }
        aSrc[i] = A + (size_t)gidx * lda + akc;
        aSz[i] = v ? 16 : 0;
        aDst[i] = (uint32_t)((arow * LDA_S + akc) * 4);
    }
#pragma unroll
    for (int i = 0; i < BCNT; i++) {
        int j = tid + i * NTHR;             // B float4 index in [0, 1024)
        int brow = j >> 5, bnc = (j & 31) * 4;
        int col = colStart + bnc;
        bool bv = (col + 4 <= N);
        bSz[i] = bv ? 16 : 0;
        bSrc[i] = B + (size_t)brow * N + (bv ? col : 0);
        bDst[i] = (uint32_t)((A_ST + brow * LDB_S + bnc) * 4);
    }

    float acc[4][4][4];
#pragma unroll
    for (int mi = 0; mi < 4; mi++)
#pragma unroll
        for (int ni = 0; ni < 4; ni++)
#pragma unroll
            for (int q = 0; q < 4; q++) acc[mi][ni][q] = 0.f;

    int KT = K / BKK;

#pragma unroll
    for (int p = 0; p < NST - 1; p++) {
        if (p < KT) {
            int k0 = p * BKK;
            uint32_t sb = sbase + (uint32_t)((p % NST) * STF * 4);
#pragma unroll
            for (int i = 0; i < ACNT; i++) cp16(sb + aDst[i], aSrc[i] + k0, aSz[i]);
#pragma unroll
            for (int i = 0; i < BCNT; i++) cp16(sb + bDst[i], bSrc[i] + (size_t)k0 * N, bSz[i]);
            asm volatile("cp.async.commit_group;");
        }
    }

    for (int it = 0; it < KT; it++) {
        if (it + NST - 1 < KT) {
            int k0 = (it + NST - 1) * BKK;
            uint32_t sb = sbase + (uint32_t)(((it + NST - 1) % NST) * STF * 4);
#pragma unroll
            for (int i = 0; i < ACNT; i++) cp16(sb + aDst[i], aSrc[i] + k0, aSz[i]);
#pragma unroll
            for (int i = 0; i < BCNT; i++) cp16(sb + bDst[i], bSrc[i] + (size_t)k0 * N, bSz[i]);
            asm volatile("cp.async.commit_group;");
        }
        int pend = KT - 1 - it;
        if (pend > NST - 1) pend = NST - 1;
        if (pend >= 2)      asm volatile("cp.async.wait_group 2;");
        else if (pend == 1) asm volatile("cp.async.wait_group 1;");
        else                asm volatile("cp.async.wait_group 0;");
        __syncthreads();

        const uint32_t* Ab = (const uint32_t*)(smem_dyn + (size_t)(it % NST) * STF);
        const uint32_t* Bb = Ab + A_ST;
#pragma unroll
        for (int ks = 0; ks < 4; ks++) {
            int kb = ks * 8;
            uint32_t af[4][4];
#pragma unroll
            for (int mi = 0; mi < 4; mi++) {
                int r = wm + mi * 16 + grp;
                af[mi][0] = Ab[r * LDA_S + kb + tig];
                af[mi][1] = Ab[(r + 8) * LDA_S + kb + tig];
                af[mi][2] = Ab[r * LDA_S + kb + tig + 4];
                af[mi][3] = Ab[(r + 8) * LDA_S + kb + tig + 4];
            }
            uint32_t bf[4][2];
#pragma unroll
            for (int ni = 0; ni < 4; ni++) {
                int ccol = wn + ni * 8 + grp;
                uint32_t r0 = Bb[(kb + tig) * LDB_S + ccol];
                uint32_t r1 = Bb[(kb + tig + 4) * LDB_S + ccol];
                if (CVTB) {
                    bf[ni][0] = f2tf32(__uint_as_float(r0));
                    bf[ni][1] = f2tf32(__uint_as_float(r1));
                } else {
                    bf[ni][0] = r0;
                    bf[ni][1] = r1;
                }
            }
#pragma unroll
            for (int mi = 0; mi < 4; mi++)
#pragma unroll
                for (int ni = 0; ni < 4; ni++)
                    mma_tf32(acc[mi][ni], af[mi], bf[ni]);
        }
        __syncthreads();
    }

    const float* bias = biasBase ? (biasBase + (long long)e * biasStride) : nullptr;
#pragma unroll
    for (int mi = 0; mi < 4; mi++) {
        int rbase = wm + mi * 16 + grp;
#pragma unroll
        for (int half = 0; half < 2; half++) {
            int r = rbase + half * 8;
            int lrow = rowTile * TBM + r;
            if (lrow >= nrows) continue;
            int grow = s0 + lrow;
#pragma unroll
            for (int ni = 0; ni < 4; ni++) {
                int col = colStart + wn + ni * 8 + tig * 2;
                float v0 = acc[mi][ni][half * 2 + 0];
                float v1 = acc[mi][ni][half * 2 + 1];
                if (bias) { v0 += bias[col]; v1 += bias[col + 1]; }
                if (doGelu) {
                    v0 = rtf(gelu_tanh(v0));
                    v1 = rtf(gelu_tanh(v1));
                }
                if (residual) {
                    v0 += residual[(size_t)grow * ldc + col];
                    v1 += residual[(size_t)grow * ldc + col + 1];
                }
                if (col < N)     C[(size_t)grow * ldc + col] = v0;
                if (col + 1 < N) C[(size_t)grow * ldc + col + 1] = v1;
            }
        }
    }
}

static inline int tg_smem_bytes(int tbm) {
    int nst = (tbm == 128) ? 3 : 2;
    return nst * (tbm * LDA_S + B_STAGE) * 4;
}

// ---------------- rmsnorm (rounded main output; optional full-precision copy) ----------------
__global__ __launch_bounds__(256) void rmsnorm_kernel(
    const float* __restrict__ x, const float* __restrict__ w,
    float* __restrict__ y, float* __restrict__ yfull)
{
    int t = blockIdx.x, tid = threadIdx.x;
    __shared__ float red[256];
    const float* xr = x + (size_t)t * DMODEL;
    float s = 0.f;
    for (int d = tid; d < DMODEL; d += 256) { float v = xr[d]; s += v * v; }
    red[tid] = s; __syncthreads();
    for (int o = 128; o > 0; o >>= 1) { if (tid < o) red[tid] += red[tid + o]; __syncthreads(); }
    float rms = rsqrtf(red[0] / (float)DMODEL + 1e-6f);
    float* yr = y + (size_t)t * DMODEL;
    for (int d = tid; d < DMODEL; d += 256) {
        float v = xr[d] * rms * w[d];
        yr[d] = rtf(v);
        if (yfull) yfull[(size_t)t * DMODEL + d] = v;
    }
}

// ---------------- indexer scores (transposed smem, vectorized LDS; fp32, bit-identical) ----------------
__global__ __launch_bounds__(256) void idx_kernel(
    const float* __restrict__ proj, float* __restrict__ out)
{
    __shared__ float qshT[64][68];
    __shared__ float kshT[64][68];
    __shared__ float hsh[64][4];
    int t0 = blockIdx.y * 64, s0 = blockIdx.x * 64;
    int tid = threadIdx.x;
    const int tr = (tid >> 4) * 4, tc = (tid & 15) * 4;

    hsh[tid >> 2][tid & 3] = proj[(size_t)(t0 + (tid >> 2)) * NPROJ_IDX + 320 + (tid & 3)];
    for (int i = tid; i < 4096; i += 256) {
        int r = i >> 6, c = i & 63;
        kshT[c][r] = proj[(size_t)(s0 + r) * NPROJ_IDX + 256 + c];
    }
    float acc[4][4];
#pragma unroll
    for (int i = 0; i < 4; i++)
#pragma unroll
        for (int j = 0; j < 4; j++) acc[i][j] = 0.f;

    for (int h = 0; h < HIDX; h++) {
        __syncthreads();
        for (int i = tid; i < 4096; i += 256) {
            int r = i >> 6, c = i & 63;
            qshT[c][r] = proj[(size_t)(t0 + r) * NPROJ_IDX + h * DIDX + c];
        }
        __syncthreads();
        float dot[4][4];
#pragma unroll
        for (int i = 0; i < 4; i++)
#pragma unroll
            for (int j = 0; j < 4; j++) dot[i][j] = 0.f;
        for (int kk = 0; kk < 64; kk++) {
            float4 a4 = *(const float4*)&qshT[kk][tr];
            float4 b4 = *(const float4*)&kshT[kk][tc];
            float a[4] = {a4.x, a4.y, a4.z, a4.w};
            float b[4] = {b4.x, b4.y, b4.z, b4.w};
#pragma unroll
            for (int i = 0; i < 4; i++)
#pragma unroll
                for (int j = 0; j < 4; j++) dot[i][j] += a[i] * b[j];
        }
#pragma unroll
        for (int i = 0; i < 4; i++)
#pragma unroll
            for (int j = 0; j < 4; j++)
                acc[i][j] += hsh[tr + i][h] * fmaxf(dot[i][j], 0.f);
    }
#pragma unroll
    for (int i = 0; i < 4; i++)
#pragma unroll
        for (int j = 0; j < 4; j++)
            out[(size_t)(t0 + tr + i) * TSEQ + (s0 + tc + j)] = acc[i][j] * 0.125f;
}

// ---------------- fused top-512 radix-select + mask build ----------------
__global__ __launch_bounds__(512) void topk_mask_kernel(
    const float* __restrict__ idxs, unsigned int* __restrict__ mask)
{
    __shared__ unsigned long long keys[2048];
    __shared__ unsigned int hist[256];
    __shared__ unsigned int sh_k;
    __shared__ unsigned long long sh_prefix;

    int t = blockIdx.x, tid = threadIdx.x;

    for (int i = tid; i < 2048; i += 512) {
        unsigned long long kk = 0ull;
        if (i <= t) {
            float v = idxs[(size_t)t * TSEQ + i];
            kk = ((unsigned long long)fmono(v) << 32) | (unsigned int)(2047 - i);
        }
        keys[i] = kk;
    }
    if (tid == 0) { sh_k = (unsigned int)KSEL; sh_prefix = 0ull; }
    __syncthreads();

    const int shifts[6] = {56, 48, 40, 32, 8, 0};
    unsigned long long prefix_mask = 0ull;
#pragma unroll
    for (int p = 0; p < 6; p++) {
        int shift = shifts[p];
        if (tid < 256) hist[tid] = 0u;
        __syncthreads();
        unsigned long long pref = sh_prefix;
        for (int i = tid; i < 2048; i += 512) {
            unsigned long long key = keys[i];
            if ((key & prefix_mask) == pref)
                atomicAdd(&hist[(unsigned int)(key >> shift) & 255u], 1u);
        }
        __syncthreads();
        for (int off = 1; off < 256; off <<= 1) {
            unsigned int add = 0u;
            if (tid < 256 && tid + off < 256) add = hist[tid + off];
            __syncthreads();
            if (tid < 256) hist[tid] += add;
            __syncthreads();
        }
        unsigned int k = sh_k;
        if (tid < 256) {
            unsigned int s_here = hist[tid];
            unsigned int s_next = (tid == 255) ? 0u : hist[tid + 1];
            if (s_here >= k && s_next < k) {
                sh_prefix = pref | ((unsigned long long)tid << shift);
                sh_k = k - s_next;
            }
        }
        __syncthreads();
        prefix_mask |= (0xFFull << shift);
    }

    unsigned long long thr = sh_prefix;
    int lane = tid & 31, w = tid >> 5;
    for (int word = w; word < 64; word += 16) {
        int i = word * 32 + lane;
        bool sel = (i <= t) && (keys[i] >= thr);
        unsigned int bal = __ballot_sync(0xFFFFFFFFu, sel);
        if (lane == 0) mask[t * 64 + word] = bal;
    }
}

// ---------------- RoPE from fused qkv + transpose to [h][t][d], rounds outputs ----------------
__global__ __launch_bounds__(256) void rope_kernel(
    const float* __restrict__ qkv,
    float* __restrict__ qh, float* __restrict__ kh, float* __restrict__ vh)
{
    int idx = blockIdx.x * 256 + threadIdx.x;
    int t = idx >> 10;
    int hd = idx & 1023;
    int h = hd >> 6, d = hd & 63;
    int j = d & 31;
    double invd = exp(-((double)(2 * j) / 64.0) * log(10000.0));
    float ang = (float)((double)t * invd);
    float c = cosf(ang), s = sinf(ang);
    const float* row = qkv + (size_t)t * NPROJ_QKV;
    float q = row[hd], k = row[DMODEL + hd], v = row[2 * DMODEL + hd];
    float qr, kr;
    if (d < 32) {
        qr = q * c - row[hd + 32] * s;
        kr = k * c - row[DMODEL + hd + 32] * s;
    } else {
        qr = q * c + row[hd - 32] * s;
        kr = k * c + row[DMODEL + hd - 32] * s;
    }
    int o = ((h * TSEQ) + t) * HDIM + d;
    qh[o] = rtf(qr); kh[o] = rtf(kr); vh[o] = rtf(v);
}

// ---------------- dense masked flash attention (tf32 mma, 128-row q tiles) ----------------
__global__ void __launch_bounds__(256, 2) attn_flash(
    const float* __restrict__ qh, const float* __restrict__ kh, const float* __restrict__ vh,
    const unsigned int* __restrict__ mask, float* __restrict__ av)
{
    __shared__ float Ks[64][68];
    __shared__ float Vs[64][68];
    __shared__ float Ps[128][68];
    __shared__ float rowM[128], rowL[128], rowScale[128];

    int qt = gridDim.x - 1 - blockIdx.x, h = blockIdx.y;
    int t0 = qt * 128;
    int tid = threadIdx.x;
    int warpId = tid >> 5, lane = tid & 31;
    int grp = lane >> 2, tig = lane & 3;
    int wm = warpId * 16;

    const float* Q0 = qh + ((size_t)h * TSEQ + t0) * HDIM;
    uint32_t qf[8][4];
#pragma unroll
    for (int ks = 0; ks < 8; ks++) {
        int kb = ks * 8;
        qf[ks][0] = __float_as_uint(Q0[(wm + grp) * HDIM + kb + tig]);
        qf[ks][1] = __float_as_uint(Q0[(wm + grp + 8) * HDIM + kb + tig]);
        qf[ks][2] = __float_as_uint(Q0[(wm + grp) * HDIM + kb + tig + 4]);
        qf[ks][3] = __float_as_uint(Q0[(wm + grp + 8) * HDIM + kb + tig + 4]);
    }

    if (tid < 128) { rowM[tid] = -INFINITY; rowL[tid] = 0.f; }

    float oacc[8][4];
#pragma unroll
    for (int ni = 0; ni < 8; ni++)
#pragma unroll
        for (int q = 0; q < 4; q++) oacc[ni][q] = 0.f;

    const float* Kb = kh + (size_t)h * TSEQ * HDIM;
    const float* Vb = vh + (size_t)h * TSEQ * HDIM;

    int ktMax = 2 * qt + 1;
    for (int kt = 0; kt <= ktMax; kt++) {
        __syncthreads();
        for (int i = tid; i < 1024; i += 256) {
            int row = i >> 4, c4 = (i & 15) * 4;
            *(float4*)&Ks[row][c4] = *(const float4*)(Kb + (size_t)(kt * 64 + row) * HDIM + c4);
            *(float4*)&Vs[row][c4] = *(const float4*)(Vb + (size_t)(kt * 64 + row) * HDIM + c4);
        }
        __syncthreads();

        float sacc[8][4];
#pragma unroll
        for (int ni = 0; ni < 8; ni++)
#pragma unroll
            for (int q = 0; q < 4; q++) sacc[ni][q] = 0.f;
#pragma unroll
        for (int ks = 0; ks < 8; ks++) {
            int kb = ks * 8;
#pragma unroll
            for (int ni = 0; ni < 8; ni++) {
                int n = ni * 8 + grp;
                uint32_t bf[2];
                bf[0] = __float_as_uint(Ks[n][kb + tig]);
                bf[1] = __float_as_uint(Ks[n][kb + tig + 4]);
                mma_tf32(sacc[ni], qf[ks], bf);
            }
        }

        int r0 = wm + grp, r1 = wm + grp + 8;
        unsigned int mw0[2], mw1[2];
        mw0[0] = mask[(t0 + r0) * 64 + kt * 2];
        mw0[1] = mask[(t0 + r0) * 64 + kt * 2 + 1];
        mw1[0] = mask[(t0 + r1) * 64 + kt * 2];
        mw1[1] = mask[(t0 + r1) * 64 + kt * 2 + 1];
#pragma unroll
        for (int ni = 0; ni < 8; ni++) {
            int c = ni * 8 + tig * 2;
            int wsel = c >> 5, b = c & 31;
            Ps[r0][c]     = ((mw0[wsel] >> b) & 1u)       ? sacc[ni][0] * 0.125f : -INFINITY;
            Ps[r0][c + 1] = ((mw0[wsel] >> (b + 1)) & 1u) ? sacc[ni][1] * 0.125f : -INFINITY;
            Ps[r1][c]     = ((mw1[wsel] >> b) & 1u)       ? sacc[ni][2] * 0.125f : -INFINITY;
            Ps[r1][c + 1] = ((mw1[wsel] >> (b + 1)) & 1u) ? sacc[ni][3] * 0.125f : -INFINITY;
        }
        __syncthreads();

#pragma unroll
        for (int rr = 0; rr < 2; rr++) {
            int row = (tid >> 2) + rr * 64, seg = tid & 3;
            float m_old = rowM[row];
            float tmax = -INFINITY;
#pragma unroll
            for (int j = 0; j < 16; j++) tmax = fmaxf(tmax, Ps[row][seg * 16 + j]);
            tmax = fmaxf(tmax, __shfl_xor_sync(0xFFFFFFFFu, tmax, 1));
            tmax = fmaxf(tmax, __shfl_xor_sync(0xFFFFFFFFu, tmax, 2));
            float mnew = fmaxf(m_old, tmax);
            bool inval = (mnew == -INFINITY);
            float tsum = 0.f;
#pragma unroll
            for (int j = 0; j < 16; j++) {
                float v = Ps[row][seg * 16 + j];
                float p = inval ? 0.f : expf(v - mnew);
                Ps[row][seg * 16 + j] = rtf(p);
                tsum += p;
            }
            tsum += __shfl_xor_sync(0xFFFFFFFFu, tsum, 1);
            tsum += __shfl_xor_sync(0xFFFFFFFFu, tsum, 2);
            if (seg == 0) {
                float sc = inval ? 1.f : expf(m_old - mnew);
                rowScale[row] = sc;
                rowM[row] = mnew;
                rowL[row] = rowL[row] * sc + tsum;
            }
        }
        __syncthreads();

        float s0 = rowScale[wm + grp], s1 = rowScale[wm + grp + 8];
#pragma unroll
        for (int ni = 0; ni < 8; ni++) {
            oacc[ni][0] *= s0; oacc[ni][1] *= s0;
            oacc[ni][2] *= s1; oacc[ni][3] *= s1;
        }
#pragma unroll
        for (int ks = 0; ks < 8; ks++) {
            int kb = ks * 8;
            uint32_t pa[4];
            pa[0] = __float_as_uint(Ps[wm + grp][kb + tig]);
            pa[1] = __float_as_uint(Ps[wm + grp + 8][kb + tig]);
            pa[2] = __float_as_uint(Ps[wm + grp][kb + tig + 4]);
            pa[3] = __float_as_uint(Ps[wm + grp + 8][kb + tig + 4]);
#pragma unroll
            for (int ni = 0; ni < 8; ni++) {
                int n = ni * 8 + grp;
                uint32_t vf[2];
                vf[0] = __float_as_uint(Vs[kb + tig][n]);
                vf[1] = __float_as_uint(Vs[kb + tig + 4][n]);
                mma_tf32(oacc[ni], pa, vf);
            }
        }
    }
    __syncthreads();

    float i0 = 1.f / rowL[wm + grp];
    float i1 = 1.f / rowL[wm + grp + 8];
#pragma unroll
    for (int ni = 0; ni < 8; ni++) {
        int c = ni * 8 + tig * 2;
        size_t o0 = (size_t)(t0 + wm + grp) * DMODEL + h * HDIM + c;
        size_t o1 = (size_t)(t0 + wm + grp + 8) * DMODEL + h * HDIM + c;
        av[o0]     = rtf(oacc[ni][0] * i0);
        av[o0 + 1] = rtf(oacc[ni][1] * i0);
        av[o1]     = rtf(oacc[ni][2] * i1);
        av[o1 + 1] = rtf(oacc[ni][3] * i1);
    }
}

// ---------------- router (reads FULL-precision x2n) ----------------
__global__ __launch_bounds__(256) void router_kernel(
    const float* __restrict__ x2n, const float* __restrict__ rw, const float* __restrict__ rb,
    float* __restrict__ probs, int* __restrict__ topE, float* __restrict__ topG)
{
    int t = blockIdx.x, tid = threadIdx.x;
    __shared__ float red[256];
    __shared__ float lg[8];
    float acc[8];
#pragma unroll
    for (int e = 0; e < 8; e++) acc[e] = 0.f;
    const float* xr = x2n + (size_t)t * DMODEL;
    for (int d = tid; d < DMODEL; d += 256) {
        float xv = xr[d];
#pragma unroll
        for (int e = 0; e < 8; e++) acc[e] += xv * rw[(size_t)d * NEXP + e];
    }
    for (int e = 0; e < 8; e++) {
        red[tid] = acc[e]; __syncthreads();
        for (int o = 128; o > 0; o >>= 1) { if (tid < o) red[tid] += red[tid + o]; __syncthreads(); }
        if (tid == 0) lg[e] = red[0] + rb[e];
        __syncthreads();
    }
    if (tid == 0) {
        float m = lg[0];
        for (int e = 1; e < 8; e++) m = fmaxf(m, lg[e]);
        float p[8], s = 0.f;
        for (int e = 0; e < 8; e++) { p[e] = expf(lg[e] - m); s += p[e]; }
        for (int e = 0; e < 8; e++) p[e] /= s;
        int e0 = 0;
        for (int e = 1; e < 8; e++) if (p[e] > p[e0]) e0 = e;
        int e1 = -1;
        for (int e = 0; e < 8; e++) if (e != e0 && (e1 < 0 || p[e] > p[e1])) e1 = e;
        float denom = p[e0] + p[e1];
        for (int e = 0; e < 8; e++) probs[(size_t)t * NEXP + e] = p[e];
        topE[t * 2 + 0] = e0; topE[t * 2 + 1] = e1;
        topG[t * 2 + 0] = p[e0] / denom; topG[t * 2 + 1] = p[e1] / denom;
    }
}

// ---------------- deterministic grouping (warp-ballot scan, order-preserving) ----------------
__global__ __launch_bounds__(256) void group_kernel(
    const int* __restrict__ topE, int* __restrict__ counts,
    int* __restrict__ segoff, int* __restrict__ rowmap,
    int* __restrict__ slotpos)
{
    __shared__ short sE[TSEQ * 2];
    __shared__ int sSeg[NEXP + 1];
    __shared__ int sCnt[NEXP];
    int tid = threadIdx.x;
    int lane = tid & 31, w = tid >> 5;
    for (int i = tid; i < TSEQ * 2; i += 256) sE[i] = (short)topE[i];
    __syncthreads();

    {
        int e = w;
        int c = 0;
        for (int i0 = 0; i0 < TSEQ * 2; i0 += 32) {
            unsigned int m = __ballot_sync(0xFFFFFFFFu, sE[i0 + lane] == e);
            c += __popc(m);
        }
        if (lane == 0) { counts[e] = c; sCnt[e] = c; }
    }
    __syncthreads();
    if (tid == 0) {
        int o = 0;
        for (int i = 0; i < 8; i++) { sSeg[i] = o; segoff[i] = o; o += sCnt[i]; }
        sSeg[8] = o; segoff[8] = o;
    }
    __syncthreads();

    {
        int e = w;
        int pos = sSeg[e];
        unsigned int ltmask = (1u << lane) - 1u;
        for (int i0 = 0; i0 < TSEQ * 2; i0 += 32) {
            int i = i0 + lane;
            bool match = (sE[i] == e);
            unsigned int m = __ballot_sync(0xFFFFFFFFu, match);
            if (match) {
                int off = __popc(m & ltmask);
                rowmap[pos + off] = i >> 1;
                slotpos[i] = pos + off;
            }
            pos += __popc(m);
        }
    }
}

// ---------------- aux loss ----------------
__global__ __launch_bounds__(256) void aux_kernel(
    const float* __restrict__ probs, const int* __restrict__ counts, float* __restrict__ outAux)
{
    __shared__ float red[256];
    int tid = threadIdx.x;
    float a = 0.f;
    for (int e = 0; e < 8; e++) {
        float s = 0.f;
        for (int t = tid; t < TSEQ; t += 256) s += probs[(size_t)t * NEXP + e];
        red[tid] = s; __syncthreads();
        for (int o = 128; o > 0; o >>= 1) { if (tid < o) red[tid] += red[tid + o]; __syncthreads(); }
        if (tid == 0) a += (float)counts[e] * red[0];
        __syncthreads();
    }
    if (tid == 0) *outAux = 8.f * a / ((float)TSEQ * (float)TSEQ);
}

// ---------------- final combine ----------------
__global__ __launch_bounds__(256) void combine_kernel(
    const float* __restrict__ x1, const float* __restrict__ y,
    const int* __restrict__ slotpos, const float* __restrict__ topG,
    float* __restrict__ out)
{
    int idx = blockIdx.x * 256 + threadIdx.x;
    int t = idx >> 10, d = idx & 1023;
    int p0 = slotpos[t * 2 + 0], p1 = slotpos[t * 2 + 1];
    float g0 = topG[t * 2 + 0], g1 = topG[t * 2 + 1];
    out[idx] = x1[idx] + g0 * y[(size_t)p0 * DMODEL + d] + g1 * y[(size_t)p1 * DMODEL + d];
}

// ---------------- host launch ----------------
#define GETSYM(ptr, sym) do { void* _p_; cudaGetSymbolAddress(&_p_, sym); ptr = (decltype(ptr))_p_; } while (0)

extern "C" void kernel_launch(void* const* d_in, const int* in_sizes, int n_in,
                              void* d_out, int out_size)
{
    const float* x        = (const float*)d_in[0];
    const float* norm1_w  = (const float*)d_in[1];
    const float* norm2_w  = (const float*)d_in[2];
    const float* wq_idx   = (const float*)d_in[3];
    const float* wk_idx   = (const float*)d_in[4];
    const float* w_head   = (const float*)d_in[5];
    const float* wq       = (const float*)d_in[6];
    const float* wk       = (const float*)d_in[7];
    const float* wv       = (const float*)d_in[8];
    const float* wo       = (const float*)d_in[9];
    const float* router_w = (const float*)d_in[10];
    const float* router_b = (const float*)d_in[11];
    const float* w1       = (const float*)d_in[12];
    const float* b1       = (const float*)d_in[13];
    const float* w2       = (const float*)d_in[14];
    const float* b2       = (const float*)d_in[15];

    float* out    = (float*)d_out;
    float* auxp   = out + (size_t)TSEQ * DMODEL;
    float* idxout = auxp + 1;

    float *p_xn, *p_proj, *p_qkv, *p_qh, *p_kh, *p_vh;
    float *p_av, *p_x1, *p_x2n, *p_x2f, *p_probs, *p_topG, *p_mid, *p_y;
    float *p_woc, *p_wqkvc, *p_widxc;
    int *p_topE, *p_counts, *p_segoff, *p_rowmap, *p_slotpos;
    unsigned int *p_mask;
    GETSYM(p_xn, g_xn); GETSYM(p_proj, g_proj_idx); GETSYM(p_qkv, g_qkv);
    GETSYM(p_qh, g_qh); GETSYM(p_kh, g_kh); GETSYM(p_vh, g_vh);
    GETSYM(p_av, g_av); GETSYM(p_x1, g_x1);
    GETSYM(p_x2n, g_x2n); GETSYM(p_x2f, g_x2f);
    GETSYM(p_probs, g_probs); GETSYM(p_topE, g_topE); GETSYM(p_topG, g_topG);
    GETSYM(p_counts, g_counts); GETSYM(p_segoff, g_segoff);
    GETSYM(p_rowmap, g_rowmap); GETSYM(p_slotpos, g_slotpos);
    GETSYM(p_mid, g_mid); GETSYM(p_y, g_yy); GETSYM(p_mask, g_mask);
    GETSYM(p_woc, g_woc); GETSYM(p_wqkvc, g_wqkvc); GETSYM(p_widxc, g_widxc);

    const int SM128 = tg_smem_bytes(128);
    const int SM256 = tg_smem_bytes(256);
    cudaFuncSetAttribute(tgemm<0, 128>, cudaFuncAttributeMaxDynamicSharedMemorySize, SM128);
    cudaFuncSetAttribute(tgemm<0, 256>, cudaFuncAttributeMaxDynamicSharedMemorySize, SM256);
    cudaFuncSetAttribute(tgemm<1, 256>, cudaFuncAttributeMaxDynamicSharedMemorySize, SM256);

    // 0. small weight rounding / packing (w1/w2 are converted inside the MoE GEMMs)
    {
        int m4 = DMODEL * DMODEL / 4;
        round4_kernel<<<(m4 + 255) / 256, 256>>>((const float4*)wo, (float4*)p_woc, m4);
        pack_qkv_kernel<<<(DMODEL * DMODEL) / 256, 256>>>(wq, wk, wv, p_wqkvc);
        pack_idx_kernel<<<(DMODEL * NPROJ_IDX + 255) / 256, 256>>>(wq_idx, wk_idx, w_head, p_widxc);
    }

    // 1. norm1
    rmsnorm_kernel<<<TSEQ, 256>>>(x, norm1_w, p_xn, nullptr);

    // 2. fused projections
    tgemm<0, 128><<<dim3((NPROJ_IDX + 127) / 128, 16, 1), 256, SM128>>>(
        p_xn, DMODEL, nullptr, p_widxc, 0, nullptr, 0,
        nullptr, p_proj, NPROJ_IDX, nullptr, TSEQ, NPROJ_IDX, DMODEL, 0);
    tgemm<0, 256><<<dim3(NPROJ_QKV / 128, 8, 1), 512, SM256>>>(
        p_xn, DMODEL, nullptr, p_wqkvc, 0, nullptr, 0,
        nullptr, p_qkv, NPROJ_QKV, nullptr, TSEQ, NPROJ_QKV, DMODEL, 0);

    // 3. indexer scores + fused top-512 mask
    idx_kernel<<<dim3(32, 32), 256>>>(p_proj, idxout);
    topk_mask_kernel<<<TSEQ, 512>>>(idxout, p_mask);

    // 4. rope + transpose
    rope_kernel<<<(TSEQ * DMODEL) / 256, 256>>>(p_qkv, p_qh, p_kh, p_vh);

    // 5. dense masked flash attention (128-row q tiles, heavy first)
    attn_flash<<<dim3(TSEQ / 128, NHEAD), 256>>>(p_qh, p_kh, p_vh, p_mask, p_av);

    // 6. output projection + residual
    tgemm<0, 256><<<dim3(8, 8, 1), 512, SM256>>>(p_av, DMODEL, nullptr, p_woc, 0, nullptr, 0,
        x, p_x1, DMODEL, nullptr, TSEQ, DMODEL, DMODEL, 0);

    // 7. norm2 + router + grouping + aux
    rmsnorm_kernel<<<TSEQ, 256>>>(p_x1, norm2_w, p_x2n, p_x2f);
    router_kernel<<<TSEQ, 256>>>(p_x2f, router_w, router_b, p_probs, p_topE, p_topG);
    group_kernel<<<1, 256>>>(p_topE, p_counts, p_segoff, p_rowmap, p_slotpos);
    aux_kernel<<<1, 256>>>(p_probs, p_counts, auxp);

    // 8. MoE grouped GEMMs (raw weights, tf32 cvt at fragment load; 256-row tiles)
    tgemm<1, 256><<<dim3(DFFN / 128, 8, NEXP), 512, SM256>>>(
        p_x2n, DMODEL, p_rowmap, w1, (long long)DMODEL * DFFN, b1, DFFN,
        nullptr, p_mid, DFFN, p_segoff, 0, DFFN, DMODEL, 1);
    tgemm<1, 256><<<dim3(DMODEL / 128, 8, NEXP), 512, SM256>>>(
        p_mid, DFFN, nullptr, w2, (long long)DFFN * DMODEL, b2, DMODEL,
        nullptr, p_y, DMODEL, p_segoff, 0, DMODEL, DFFN, 0);

    // 9. combine
    combine_kernel<<<(TSEQ * DMODEL) / 256, 256>>>(p_x1, p_y, p_slotpos, p_topG, out);
}

// round 10
// speedup vs baseline: 1.1319x; 1.1319x over previous
#include <cuda_runtime.h>
#include <math.h>
#include <stdint.h>

// ---------------- constants ----------------
static const int TSEQ = 2048;
static const int DMODEL = 1024;
static const int NHEAD = 16;
static const int HDIM = 64;
static const int DFFN = 4096;
static const int NEXP = 8;
static const int HIDX = 4;
static const int DIDX = 64;
static const int KSEL = 512;
static const int NALL = 3 * DMODEL + HIDX * DIDX + DIDX + HIDX;  // 3396 fused proj width
static const int OFF_Q = 0;
static const int OFF_K = DMODEL;
static const int OFF_V = 2 * DMODEL;
static const int OFF_QI = 3 * DMODEL;          // 3072
static const int OFF_KI = OFF_QI + HIDX * DIDX; // 3328
static const int OFF_HW = OFF_KI + DIDX;        // 3392

// ---------------- device scratch ----------------
__device__ float g_xn[TSEQ * DMODEL];
__device__ float g_all[TSEQ * NALL];            // fused projection output
__device__ float g_qh[TSEQ * DMODEL];
__device__ float g_kh[TSEQ * DMODEL];
__device__ float g_vh[TSEQ * DMODEL];
__device__ float g_av[TSEQ * DMODEL];
__device__ float g_x1[TSEQ * DMODEL];
__device__ float g_x2n[TSEQ * DMODEL];   // tf32-rounded (GEMM operand)
__device__ float g_x2f[TSEQ * DMODEL];   // full fp32 (router input)
__device__ float g_probs[TSEQ * NEXP];
__device__ int   g_topE[TSEQ * 2];
__device__ float g_topG[TSEQ * 2];
__device__ int   g_counts[NEXP];
__device__ int   g_segoff[NEXP + 1];
__device__ int   g_rowmap[TSEQ * 2];
__device__ int   g_slotpos[TSEQ * 2];
__device__ float g_mid[(size_t)(TSEQ * 2) * DFFN];
__device__ float g_yy[(size_t)(TSEQ * 2) * DMODEL];
__device__ unsigned int g_mask[TSEQ * (TSEQ / 32)];
// tf32-rounded packed weights (small; w1/w2 converted in-GEMM)
__device__ float g_woc[DMODEL * DMODEL];
__device__ float g_wall[DMODEL * NALL];

// ---------------- helpers ----------------
__device__ __forceinline__ float gelu_tanh(float x) {
    float x3 = x * x * x;
    float u = 0.7978845608028654f * (x + 0.044715f * x3);
    return 0.5f * x * (1.0f + tanhf(u));
}

__device__ __forceinline__ unsigned int fmono(float f) {
    unsigned int u = __float_as_uint(f);
    return (u & 0x80000000u) ? ~u : (u | 0x80000000u);
}

__device__ __forceinline__ uint32_t f2tf32(float f) {
    uint32_t r;
    asm("cvt.rna.tf32.f32 %0, %1;" : "=r"(r) : "f"(f));
    return r;
}
__device__ __forceinline__ float rtf(float f) { return __uint_as_float(f2tf32(f)); }

__device__ __forceinline__ void cp16(uint32_t dst, const float* src, int sz) {
    asm volatile("cp.async.cg.shared.global [%0], [%1], 16, %2;" :: "r"(dst), "l"(src), "r"(sz));
}

__device__ __forceinline__ void mma_tf32(float* c, const uint32_t* a, const uint32_t* b) {
    asm volatile(
        "mma.sync.aligned.m16n8k8.row.col.f32.tf32.tf32.f32 "
        "{%0,%1,%2,%3}, {%4,%5,%6,%7}, {%8,%9}, {%0,%1,%2,%3};"
        : "+f"(c[0]), "+f"(c[1]), "+f"(c[2]), "+f"(c[3])
        : "r"(a[0]), "r"(a[1]), "r"(a[2]), "r"(a[3]), "r"(b[0]), "r"(b[1]));
}

// ---------------- weight rounding / packing ----------------
__global__ __launch_bounds__(256) void round4_kernel(
    const float4* __restrict__ in, float4* __restrict__ out, int n4)
{
    int i = blockIdx.x * 256 + threadIdx.x;
    if (i < n4) {
        float4 v = in[i];
        v.x = rtf(v.x); v.y = rtf(v.y); v.z = rtf(v.z); v.w = rtf(v.w);
        out[i] = v;
    }
}

// pack wq|wk|wv|wq_idx|wk_idx|w_head into one [1024][3396] tf32-rounded matrix
__global__ __launch_bounds__(256) void pack_all_kernel(
    const float* __restrict__ wq, const float* __restrict__ wk, const float* __restrict__ wv,
    const float* __restrict__ wq_idx, const float* __restrict__ wk_idx,
    const float* __restrict__ w_head, float* __restrict__ out)
{
    int i = blockIdx.x * 256 + threadIdx.x;  // over 1024*3396
    if (i >= DMODEL * NALL) return;
    int d = i / NALL, j = i - d * NALL;
    float v;
    if (j < OFF_K)        v = wq[d * DMODEL + j];
    else if (j < OFF_V)   v = wk[d * DMODEL + (j - OFF_K)];
    else if (j < OFF_QI)  v = wv[d * DMODEL + (j - OFF_V)];
    else if (j < OFF_KI)  v = wq_idx[d * (HIDX * DIDX) + (j - OFF_QI)];
    else if (j < OFF_HW)  v = wk_idx[d * DIDX + (j - OFF_KI)];
    else                  v = w_head[d * HIDX + (j - OFF_HW)];
    out[i] = rtf(v);
}

// ---------------- unified tf32 tensor GEMM (TBM=128, 3-stage, 2 CTA/SM) ----------------
// CVTB=1: B raw fp32, rounded at fragment load (bit-identical to pre-rounded copy).
#define BKM 128
#define BKK 32
#define LDA_S 36
#define LDB_S 132
#define A_STAGE (BKM * LDA_S)
#define B_STAGE (BKK * LDB_S)
#define STAGE_FLOATS (A_STAGE + B_STAGE)
#define NSTAGE 3
#define TG_SMEM_BYTES (NSTAGE * STAGE_FLOATS * 4)

extern __shared__ float smem_dyn[];

template <int CVTB>
__global__ void __launch_bounds__(256, 2) tgemm(
    const float* __restrict__ A, int lda,
    const int* __restrict__ rowmap,
    const float* __restrict__ Bbase, long long strideB,
    const float* __restrict__ biasBase, int biasStride,
    const float* __restrict__ residual,
    float* __restrict__ C, int ldc,
    const int* __restrict__ segoff,
    int M, int N, int K, int doGelu)
{
    int e = blockIdx.z;
    int s0 = 0, nrows = M;
    if (segoff) { s0 = segoff[e]; nrows = segoff[e + 1] - s0; }
    int rowTile = blockIdx.y;
    if (rowTile * BKM >= nrows) return;
    int colStart = blockIdx.x * 128;
    const float* B = Bbase + (long long)e * strideB;

    int tid = threadIdx.x;
    int warpId = tid >> 5, lane = tid & 31;
    int grp = lane >> 2, tig = lane & 3;
    int wm = (warpId >> 2) * 64;
    int wn = (warpId & 3) * 32;

    uint32_t sbase = (uint32_t)__cvta_generic_to_shared(smem_dyn);

    const float* aSrc[4]; int aSz[4]; uint32_t aDst[4];
    const float* bSrc[4]; int bSz[4]; uint32_t bDst[4];
#pragma unroll
    for (int i = 0; i < 4; i++) {
        int c = tid + i * 256;
        int arow = c >> 3, akc = (c & 7) * 4;
        int lrow = rowTile * BKM + arow;
        bool v = lrow < nrows;
        int gidx = 0;
        if (v) {
            int base = s0 + lrow;
            gidx = rowmap ? rowmap[base] : base;
        }
        aSrc[i] = A + (size_t)gidx * lda + akc;
        aSz[i] = v ? 16 : 0;
        aDst[i] = (uint32_t)((arow * LDA_S + akc) * 4);

        int brow = c >> 5, bnc = (c & 31) * 4;
        int col = colStart + bnc;
        bool bv = (col + 4 <= N);
        bSz[i] = bv ? 16 : 0;
        bSrc[i] = B + (size_t)brow * N + (bv ? col : 0);
        bDst[i] = (uint32_t)((A_STAGE + brow * LDB_S + bnc) * 4);
    }

    float acc[4][4][4];
#pragma unroll
    for (int mi = 0; mi < 4; mi++)
#pragma unroll
        for (int ni = 0; ni < 4; ni++)
#pragma unroll
            for (int q = 0; q < 4; q++) acc[mi][ni][q] = 0.f;

    int KT = K / BKK;

#pragma unroll
    for (int p = 0; p < NSTAGE - 1; p++) {
        if (p < KT) {
            int k0 = p * BKK;
            uint32_t sb = sbase + (uint32_t)((p % NSTAGE) * STAGE_FLOATS * 4);
#pragma unroll
            for (int i = 0; i < 4; i++) cp16(sb + aDst[i], aSrc[i] + k0, aSz[i]);
#pragma unroll
            for (int i = 0; i < 4; i++) cp16(sb + bDst[i], bSrc[i] + (size_t)k0 * N, bSz[i]);
            asm volatile("cp.async.commit_group;");
        }
    }

    for (int it = 0; it < KT; it++) {
        if (it + NSTAGE - 1 < KT) {
            int k0 = (it + NSTAGE - 1) * BKK;
            uint32_t sb = sbase + (uint32_t)(((it + NSTAGE - 1) % NSTAGE) * STAGE_FLOATS * 4);
#pragma unroll
            for (int i = 0; i < 4; i++) cp16(sb + aDst[i], aSrc[i] + k0, aSz[i]);
#pragma unroll
            for (int i = 0; i < 4; i++) cp16(sb + bDst[i], bSrc[i] + (size_t)k0 * N, bSz[i]);
            asm volatile("cp.async.commit_group;");
        }
        int pend = KT - 1 - it;
        if (pend > NSTAGE - 1) pend = NSTAGE - 1;
        if (pend >= 2)      asm volatile("cp.async.wait_group 2;");
        else if (pend == 1) asm volatile("cp.async.wait_group 1;");
        else                asm volatile("cp.async.wait_group 0;");
        __syncthreads();

        const uint32_t* Ab = (const uint32_t*)(smem_dyn + (size_t)(it % NSTAGE) * STAGE_FLOATS);
        const uint32_t* Bb = Ab + A_STAGE;
#pragma unroll
        for (int ks = 0; ks < 4; ks++) {
            int kb = ks * 8;
            uint32_t af[4][4];
#pragma unroll
            for (int mi = 0; mi < 4; mi++) {
                int r = wm + mi * 16 + grp;
                af[mi][0] = Ab[r * LDA_S + kb + tig];
                af[mi][1] = Ab[(r + 8) * LDA_S + kb + tig];
                af[mi][2] = Ab[r * LDA_S + kb + tig + 4];
                af[mi][3] = Ab[(r + 8) * LDA_S + kb + tig + 4];
            }
            uint32_t bf[4][2];
#pragma unroll
            for (int ni = 0; ni < 4; ni++) {
                int ccol = wn + ni * 8 + grp;
                uint32_t r0 = Bb[(kb + tig) * LDB_S + ccol];
                uint32_t r1 = Bb[(kb + tig + 4) * LDB_S + ccol];
                if (CVTB) {
                    bf[ni][0] = f2tf32(__uint_as_float(r0));
                    bf[ni][1] = f2tf32(__uint_as_float(r1));
                } else {
                    bf[ni][0] = r0;
                    bf[ni][1] = r1;
                }
            }
#pragma unroll
            for (int mi = 0; mi < 4; mi++)
#pragma unroll
                for (int ni = 0; ni < 4; ni++)
                    mma_tf32(acc[mi][ni], af[mi], bf[ni]);
        }
        __syncthreads();
    }

    const float* bias = biasBase ? (biasBase + (long long)e * biasStride) : nullptr;
#pragma unroll
    for (int mi = 0; mi < 4; mi++) {
        int rbase = wm + mi * 16 + grp;
#pragma unroll
        for (int half = 0; half < 2; half++) {
            int r = rbase + half * 8;
            int lrow = rowTile * BKM + r;
            if (lrow >= nrows) continue;
            int grow = s0 + lrow;
#pragma unroll
            for (int ni = 0; ni < 4; ni++) {
                int col = colStart + wn + ni * 8 + tig * 2;
                float v0 = acc[mi][ni][half * 2 + 0];
                float v1 = acc[mi][ni][half * 2 + 1];
                if (bias) { v0 += bias[col]; v1 += bias[col + 1]; }
                if (doGelu) {
                    v0 = rtf(gelu_tanh(v0));
                    v1 = rtf(gelu_tanh(v1));
                }
                if (residual) {
                    v0 += residual[(size_t)grow * ldc + col];
                    v1 += residual[(size_t)grow * ldc + col + 1];
                }
                if (col < N)     C[(size_t)grow * ldc + col] = v0;
                if (col + 1 < N) C[(size_t)grow * ldc + col + 1] = v1;
            }
        }
    }
}

// ---------------- rmsnorm (rounded main output; optional full-precision copy) ----------------
__global__ __launch_bounds__(256) void rmsnorm_kernel(
    const float* __restrict__ x, const float* __restrict__ w,
    float* __restrict__ y, float* __restrict__ yfull)
{
    int t = blockIdx.x, tid = threadIdx.x;
    __shared__ float red[256];
    const float* xr = x + (size_t)t * DMODEL;
    float s = 0.f;
    for (int d = tid; d < DMODEL; d += 256) { float v = xr[d]; s += v * v; }
    red[tid] = s; __syncthreads();
    for (int o = 128; o > 0; o >>= 1) { if (tid < o) red[tid] += red[tid + o]; __syncthreads(); }
    float rms = rsqrtf(red[0] / (float)DMODEL + 1e-6f);
    float* yr = y + (size_t)t * DMODEL;
    for (int d = tid; d < DMODEL; d += 256) {
        float v = xr[d] * rms * w[d];
        yr[d] = rtf(v);
        if (yfull) yfull[(size_t)t * DMODEL + d] = v;
    }
}

// ---------------- indexer scores (reads fused proj buffer, stride NALL) ----------------
__global__ __launch_bounds__(256) void idx_kernel(
    const float* __restrict__ proj, float* __restrict__ out)
{
    __shared__ float qshT[64][68];
    __shared__ float kshT[64][68];
    __shared__ float hsh[64][4];
    int t0 = blockIdx.y * 64, s0 = blockIdx.x * 64;
    int tid = threadIdx.x;
    const int tr = (tid >> 4) * 4, tc = (tid & 15) * 4;

    hsh[tid >> 2][tid & 3] = proj[(size_t)(t0 + (tid >> 2)) * NALL + OFF_HW + (tid & 3)];
    for (int i = tid; i < 4096; i += 256) {
        int r = i >> 6, c = i & 63;
        kshT[c][r] = proj[(size_t)(s0 + r) * NALL + OFF_KI + c];
    }
    float acc[4][4];
#pragma unroll
    for (int i = 0; i < 4; i++)
#pragma unroll
        for (int j = 0; j < 4; j++) acc[i][j] = 0.f;

    for (int h = 0; h < HIDX; h++) {
        __syncthreads();
        for (int i = tid; i < 4096; i += 256) {
            int r = i >> 6, c = i & 63;
            qshT[c][r] = proj[(size_t)(t0 + r) * NALL + OFF_QI + h * DIDX + c];
        }
        __syncthreads();
        float dot[4][4];
#pragma unroll
        for (int i = 0; i < 4; i++)
#pragma unroll
            for (int j = 0; j < 4; j++) dot[i][j] = 0.f;
        for (int kk = 0; kk < 64; kk++) {
            float4 a4 = *(const float4*)&qshT[kk][tr];
            float4 b4 = *(const float4*)&kshT[kk][tc];
            float a[4] = {a4.x, a4.y, a4.z, a4.w};
            float b[4] = {b4.x, b4.y, b4.z, b4.w};
#pragma unroll
            for (int i = 0; i < 4; i++)
#pragma unroll
                for (int j = 0; j < 4; j++) dot[i][j] += a[i] * b[j];
        }
#pragma unroll
        for (int i = 0; i < 4; i++)
#pragma unroll
            for (int j = 0; j < 4; j++)
                acc[i][j] += hsh[tr + i][h] * fmaxf(dot[i][j], 0.f);
    }
#pragma unroll
    for (int i = 0; i < 4; i++)
#pragma unroll
        for (int j = 0; j < 4; j++)
            out[(size_t)(t0 + tr + i) * TSEQ + (s0 + tc + j)] = acc[i][j] * 0.125f;
}

// ---------------- fused top-512 radix-select + mask build ----------------
__global__ __launch_bounds__(512) void topk_mask_kernel(
    const float* __restrict__ idxs, unsigned int* __restrict__ mask)
{
    __shared__ unsigned long long keys[2048];
    __shared__ unsigned int hist[256];
    __shared__ unsigned int sh_k;
    __shared__ unsigned long long sh_prefix;

    int t = blockIdx.x, tid = threadIdx.x;

    for (int i = tid; i < 2048; i += 512) {
        unsigned long long kk = 0ull;
        if (i <= t) {
            float v = idxs[(size_t)t * TSEQ + i];
            kk = ((unsigned long long)fmono(v) << 32) | (unsigned int)(2047 - i);
        }
        keys[i] = kk;
    }
    if (tid == 0) { sh_k = (unsigned int)KSEL; sh_prefix = 0ull; }
    __syncthreads();

    const int shifts[6] = {56, 48, 40, 32, 8, 0};
    unsigned long long prefix_mask = 0ull;
#pragma unroll
    for (int p = 0; p < 6; p++) {
        int shift = shifts[p];
        if (tid < 256) hist[tid] = 0u;
        __syncthreads();
        unsigned long long pref = sh_prefix;
        for (int i = tid; i < 2048; i += 512) {
            unsigned long long key = keys[i];
            if ((key & prefix_mask) == pref)
                atomicAdd(&hist[(unsigned int)(key >> shift) & 255u], 1u);
        }
        __syncthreads();
        for (int off = 1; off < 256; off <<= 1) {
            unsigned int add = 0u;
            if (tid < 256 && tid + off < 256) add = hist[tid + off];
            __syncthreads();
            if (tid < 256) hist[tid] += add;
            __syncthreads();
        }
        unsigned int k = sh_k;
        if (tid < 256) {
            unsigned int s_here = hist[tid];
            unsigned int s_next = (tid == 255) ? 0u : hist[tid + 1];
            if (s_here >= k && s_next < k) {
                sh_prefix = pref | ((unsigned long long)tid << shift);
                sh_k = k - s_next;
            }
        }
        __syncthreads();
        prefix_mask |= (0xFFull << shift);
    }

    unsigned long long thr = sh_prefix;
    int lane = tid & 31, w = tid >> 5;
    for (int word = w; word < 64; word += 16) {
        int i = word * 32 + lane;
        bool sel = (i <= t) && (keys[i] >= thr);
        unsigned int bal = __ballot_sync(0xFFFFFFFFu, sel);
        if (lane == 0) mask[t * 64 + word] = bal;
    }
}

// ---------------- RoPE from fused proj + transpose to [h][t][d], rounds outputs ----------------
__global__ __launch_bounds__(256) void rope_kernel(
    const float* __restrict__ proj,
    float* __restrict__ qh, float* __restrict__ kh, float* __restrict__ vh)
{
    int idx = blockIdx.x * 256 + threadIdx.x;
    int t = idx >> 10;
    int hd = idx & 1023;
    int h = hd >> 6, d = hd & 63;
    int j = d & 31;
    double invd = exp(-((double)(2 * j) / 64.0) * log(10000.0));
    float ang = (float)((double)t * invd);
    float c = cosf(ang), s = sinf(ang);
    const float* row = proj + (size_t)t * NALL;
    float q = row[OFF_Q + hd], k = row[OFF_K + hd], v = row[OFF_V + hd];
    float qr, kr;
    if (d < 32) {
        qr = q * c - row[OFF_Q + hd + 32] * s;
        kr = k * c - row[OFF_K + hd + 32] * s;
    } else {
        qr = q * c + row[OFF_Q + hd - 32] * s;
        kr = k * c + row[OFF_K + hd - 32] * s;
    }
    int o = ((h * TSEQ) + t) * HDIM + d;
    qh[o] = rtf(qr); kh[o] = rtf(kr); vh[o] = rtf(v);
}

// ---------------- dense masked flash attention (tf32 mma, 128-row q tiles) ----------------
__global__ void __launch_bounds__(256, 2) attn_flash(
    const float* __restrict__ qh, const float* __restrict__ kh, const float* __restrict__ vh,
    const unsigned int* __restrict__ mask, float* __restrict__ av)
{
    __shared__ float Ks[64][68];
    __shared__ float Vs[64][68];
    __shared__ float Ps[128][68];
    __shared__ float rowM[128], rowL[128], rowScale[128];

    int qt = gridDim.x - 1 - blockIdx.x, h = blockIdx.y;
    int t0 = qt * 128;
    int tid = threadIdx.x;
    int warpId = tid >> 5, lane = tid & 31;
    int grp = lane >> 2, tig = lane & 3;
    int wm = warpId * 16;

    const float* Q0 = qh + ((size_t)h * TSEQ + t0) * HDIM;
    uint32_t qf[8][4];
#pragma unroll
    for (int ks = 0; ks < 8; ks++) {
        int kb = ks * 8;
        qf[ks][0] = __float_as_uint(Q0[(wm + grp) * HDIM + kb + tig]);
        qf[ks][1] = __float_as_uint(Q0[(wm + grp + 8) * HDIM + kb + tig]);
        qf[ks][2] = __float_as_uint(Q0[(wm + grp) * HDIM + kb + tig + 4]);
        qf[ks][3] = __float_as_uint(Q0[(wm + grp + 8) * HDIM + kb + tig + 4]);
    }

    if (tid < 128) { rowM[tid] = -INFINITY; rowL[tid] = 0.f; }

    float oacc[8][4];
#pragma unroll
    for (int ni = 0; ni < 8; ni++)
#pragma unroll
        for (int q = 0; q < 4; q++) oacc[ni][q] = 0.f;

    const float* Kb = kh + (size_t)h * TSEQ * HDIM;
    const float* Vb = vh + (size_t)h * TSEQ * HDIM;

    int ktMax = 2 * qt + 1;
    for (int kt = 0; kt <= ktMax; kt++) {
        __syncthreads();
        for (int i = tid; i < 1024; i += 256) {
            int row = i >> 4, c4 = (i & 15) * 4;
            *(float4*)&Ks[row][c4] = *(const float4*)(Kb + (size_t)(kt * 64 + row) * HDIM + c4);
            *(float4*)&Vs[row][c4] = *(const float4*)(Vb + (size_t)(kt * 64 + row) * HDIM + c4);
        }
        __syncthreads();

        float sacc[8][4];
#pragma unroll
        for (int ni = 0; ni < 8; ni++)
#pragma unroll
            for (int q = 0; q < 4; q++) sacc[ni][q] = 0.f;
#pragma unroll
        for (int ks = 0; ks < 8; ks++) {
            int kb = ks * 8;
#pragma unroll
            for (int ni = 0; ni < 8; ni++) {
                int n = ni * 8 + grp;
                uint32_t bf[2];
                bf[0] = __float_as_uint(Ks[n][kb + tig]);
                bf[1] = __float_as_uint(Ks[n][kb + tig + 4]);
                mma_tf32(sacc[ni], qf[ks], bf);
            }
        }

        int r0 = wm + grp, r1 = wm + grp + 8;
        unsigned int mw0[2], mw1[2];
        mw0[0] = mask[(t0 + r0) * 64 + kt * 2];
        mw0[1] = mask[(t0 + r0) * 64 + kt * 2 + 1];
        mw1[0] = mask[(t0 + r1) * 64 + kt * 2];
        mw1[1] = mask[(t0 + r1) * 64 + kt * 2 + 1];
#pragma unroll
        for (int ni = 0; ni < 8; ni++) {
            int c = ni * 8 + tig * 2;
            int wsel = c >> 5, b = c & 31;
            Ps[r0][c]     = ((mw0[wsel] >> b) & 1u)       ? sacc[ni][0] * 0.125f : -INFINITY;
            Ps[r0][c + 1] = ((mw0[wsel] >> (b + 1)) & 1u) ? sacc[ni][1] * 0.125f : -INFINITY;
            Ps[r1][c]     = ((mw1[wsel] >> b) & 1u)       ? sacc[ni][2] * 0.125f : -INFINITY;
            Ps[r1][c + 1] = ((mw1[wsel] >> (b + 1)) & 1u) ? sacc[ni][3] * 0.125f : -INFINITY;
        }
        __syncthreads();

#pragma unroll
        for (int rr = 0; rr < 2; rr++) {
            int row = (tid >> 2) + rr * 64, seg = tid & 3;
            float m_old = rowM[row];
            float tmax = -INFINITY;
#pragma unroll
            for (int j = 0; j < 16; j++) tmax = fmaxf(tmax, Ps[row][seg * 16 + j]);
            tmax = fmaxf(tmax, __shfl_xor_sync(0xFFFFFFFFu, tmax, 1));
            tmax = fmaxf(tmax, __shfl_xor_sync(0xFFFFFFFFu, tmax, 2));
            float mnew = fmaxf(m_old, tmax);
            bool inval = (mnew == -INFINITY);
            float tsum = 0.f;
#pragma unroll
            for (int j = 0; j < 16; j++) {
                float v = Ps[row][seg * 16 + j];
                float p = inval ? 0.f : expf(v - mnew);
                Ps[row][seg * 16 + j] = rtf(p);
                tsum += p;
            }
            tsum += __shfl_xor_sync(0xFFFFFFFFu, tsum, 1);
            tsum += __shfl_xor_sync(0xFFFFFFFFu, tsum, 2);
            if (seg == 0) {
                float sc = inval ? 1.f : expf(m_old - mnew);
                rowScale[row] = sc;
                rowM[row] = mnew;
                rowL[row] = rowL[row] * sc + tsum;
            }
        }
        __syncthreads();

        float s0 = rowScale[wm + grp], s1 = rowScale[wm + grp + 8];
#pragma unroll
        for (int ni = 0; ni < 8; ni++) {
            oacc[ni][0] *= s0; oacc[ni][1] *= s0;
            oacc[ni][2] *= s1; oacc[ni][3] *= s1;
        }
#pragma unroll
        for (int ks = 0; ks < 8; ks++) {
            int kb = ks * 8;
            uint32_t pa[4];
            pa[0] = __float_as_uint(Ps[wm + grp][kb + tig]);
            pa[1] = __float_as_uint(Ps[wm + grp + 8][kb + tig]);
            pa[2] = __float_as_uint(Ps[wm + grp][kb + tig + 4]);
            pa[3] = __float_as_uint(Ps[wm + grp + 8][kb + tig + 4]);
#pragma unroll
            for (int ni = 0; ni < 8; ni++) {
                int n = ni * 8 + grp;
                uint32_t vf[2];
                vf[0] = __float_as_uint(Vs[kb + tig][n]);
                vf[1] = __float_as_uint(Vs[kb + tig + 4][n]);
                mma_tf32(oacc[ni], pa, vf);
            }
        }
    }
    __syncthreads();

    float i0 = 1.f / rowL[wm + grp];
    float i1 = 1.f / rowL[wm + grp + 8];
#pragma unroll
    for (int ni = 0; ni < 8; ni++) {
        int c = ni * 8 + tig * 2;
        size_t o0 = (size_t)(t0 + wm + grp) * DMODEL + h * HDIM + c;
        size_t o1 = (size_t)(t0 + wm + grp + 8) * DMODEL + h * HDIM + c;
        av[o0]     = rtf(oacc[ni][0] * i0);
        av[o0 + 1] = rtf(oacc[ni][1] * i0);
        av[o1]     = rtf(oacc[ni][2] * i1);
        av[o1 + 1] = rtf(oacc[ni][3] * i1);
    }
}

// ---------------- router (reads FULL-precision x2n) ----------------
__global__ __launch_bounds__(256) void router_kernel(
    const float* __restrict__ x2n, const float* __restrict__ rw, const float* __restrict__ rb,
    float* __restrict__ probs, int* __restrict__ topE, float* __restrict__ topG)
{
    int t = blockIdx.x, tid = threadIdx.x;
    __shared__ float red[256];
    __shared__ float lg[8];
    float acc[8];
#pragma unroll
    for (int e = 0; e < 8; e++) acc[e] = 0.f;
    const float* xr = x2n + (size_t)t * DMODEL;
    for (int d = tid; d < DMODEL; d += 256) {
        float xv = xr[d];
#pragma unroll
        for (int e = 0; e < 8; e++) acc[e] += xv * rw[(size_t)d * NEXP + e];
    }
    for (int e = 0; e < 8; e++) {
        red[tid] = acc[e]; __syncthreads();
        for (int o = 128; o > 0; o >>= 1) { if (tid < o) red[tid] += red[tid + o]; __syncthreads(); }
        if (tid == 0) lg[e] = red[0] + rb[e];
        __syncthreads();
    }
    if (tid == 0) {
        float m = lg[0];
        for (int e = 1; e < 8; e++) m = fmaxf(m, lg[e]);
        float p[8], s = 0.f;
        for (int e = 0; e < 8; e++) { p[e] = expf(lg[e] - m); s += p[e]; }
        for (int e = 0; e < 8; e++) p[e] /= s;
        int e0 = 0;
        for (int e = 1; e < 8; e++) if (p[e] > p[e0]) e0 = e;
        int e1 = -1;
        for (int e = 0; e < 8; e++) if (e != e0 && (e1 < 0 || p[e] > p[e1])) e1 = e;
        float denom = p[e0] + p[e1];
        for (int e = 0; e < 8; e++) probs[(size_t)t * NEXP + e] = p[e];
        topE[t * 2 + 0] = e0; topE[t * 2 + 1] = e1;
        topG[t * 2 + 0] = p[e0] / denom; topG[t * 2 + 1] = p[e1] / denom;
    }
}

// ---------------- deterministic grouping (warp-ballot scan, order-preserving) ----------------
__global__ __launch_bounds__(256) void group_kernel(
    const int* __restrict__ topE, int* __restrict__ counts,
    int* __restrict__ segoff, int* __restrict__ rowmap,
    int* __restrict__ slotpos)
{
    __shared__ short sE[TSEQ * 2];
    __shared__ int sSeg[NEXP + 1];
    __shared__ int sCnt[NEXP];
    int tid = threadIdx.x;
    int lane = tid & 31, w = tid >> 5;
    for (int i = tid; i < TSEQ * 2; i += 256) sE[i] = (short)topE[i];
    __syncthreads();

    {
        int e = w;
        int c = 0;
        for (int i0 = 0; i0 < TSEQ * 2; i0 += 32) {
            unsigned int m = __ballot_sync(0xFFFFFFFFu, sE[i0 + lane] == e);
            c += __popc(m);
        }
        if (lane == 0) { counts[e] = c; sCnt[e] = c; }
    }
    __syncthreads();
    if (tid == 0) {
        int o = 0;
        for (int i = 0; i < 8; i++) { sSeg[i] = o; segoff[i] = o; o += sCnt[i]; }
        sSeg[8] = o; segoff[8] = o;
    }
    __syncthreads();

    {
        int e = w;
        int pos = sSeg[e];
        unsigned int ltmask = (1u << lane) - 1u;
        for (int i0 = 0; i0 < TSEQ * 2; i0 += 32) {
            int i = i0 + lane;
            bool match = (sE[i] == e);
            unsigned int m = __ballot_sync(0xFFFFFFFFu, match);
            if (match) {
                int off = __popc(m & ltmask);
                rowmap[pos + off] = i >> 1;
                slotpos[i] = pos + off;
            }
            pos += __popc(m);
        }
    }
}

// ---------------- aux loss ----------------
__global__ __launch_bounds__(256) void aux_kernel(
    const float* __restrict__ probs, const int* __restrict__ counts, float* __restrict__ outAux)
{
    __shared__ float red[256];
    int tid = threadIdx.x;
    float a = 0.f;
    for (int e = 0; e < 8; e++) {
        float s = 0.f;
        for (int t = tid; t < TSEQ; t += 256) s += probs[(size_t)t * NEXP + e];
        red[tid] = s; __syncthreads();
        for (int o = 128; o > 0; o >>= 1) { if (tid < o) red[tid] += red[tid + o]; __syncthreads(); }
        if (tid == 0) a += (float)counts[e] * red[0];
        __syncthreads();
    }
    if (tid == 0) *outAux = 8.f * a / ((float)TSEQ * (float)TSEQ);
}

// ---------------- final combine (float4 vectorized, elementwise) ----------------
__global__ __launch_bounds__(256) void combine_kernel(
    const float* __restrict__ x1, const float* __restrict__ y,
    const int* __restrict__ slotpos, const float* __restrict__ topG,
    float* __restrict__ out)
{
    int i4 = blockIdx.x * 256 + threadIdx.x;   // over TSEQ*DMODEL/4
    int t = i4 >> 8, d4 = (i4 & 255) * 4;
    int p0 = slotpos[t * 2 + 0], p1 = slotpos[t * 2 + 1];
    float g0 = topG[t * 2 + 0], g1 = topG[t * 2 + 1];
    float4 a = *(const float4*)(x1 + (size_t)t * DMODEL + d4);
    float4 y0 = *(const float4*)(y + (size_t)p0 * DMODEL + d4);
    float4 y1 = *(const float4*)(y + (size_t)p1 * DMODEL + d4);
    float4 r;
    r.x = a.x + g0 * y0.x + g1 * y1.x;
    r.y = a.y + g0 * y0.y + g1 * y1.y;
    r.z = a.z + g0 * y0.z + g1 * y1.z;
    r.w = a.w + g0 * y0.w + g1 * y1.w;
    *(float4*)(out + (size_t)t * DMODEL + d4) = r;
}

// ---------------- host launch ----------------
#define GETSYM(ptr, sym) do { void* _p_; cudaGetSymbolAddress(&_p_, sym); ptr = (decltype(ptr))_p_; } while (0)

extern "C" void kernel_launch(void* const* d_in, const int* in_sizes, int n_in,
                              void* d_out, int out_size)
{
    const float* x        = (const float*)d_in[0];
    const float* norm1_w  = (const float*)d_in[1];
    const float* norm2_w  = (const float*)d_in[2];
    const float* wq_idx   = (const float*)d_in[3];
    const float* wk_idx   = (const float*)d_in[4];
    const float* w_head   = (const float*)d_in[5];
    const float* wq       = (const float*)d_in[6];
    const float* wk       = (const float*)d_in[7];
    const float* wv       = (const float*)d_in[8];
    const float* wo       = (const float*)d_in[9];
    const float* router_w = (const float*)d_in[10];
    const float* router_b = (const float*)d_in[11];
    const float* w1       = (const float*)d_in[12];
    const float* b1       = (const float*)d_in[13];
    const float* w2       = (const float*)d_in[14];
    const float* b2       = (const float*)d_in[15];

    float* out    = (float*)d_out;
    float* auxp   = out + (size_t)TSEQ * DMODEL;
    float* idxout = auxp + 1;

    float *p_xn, *p_all, *p_qh, *p_kh, *p_vh;
    float *p_av, *p_x1, *p_x2n, *p_x2f, *p_probs, *p_topG, *p_mid, *p_y;
    float *p_woc, *p_wall;
    int *p_topE, *p_counts, *p_segoff, *p_rowmap, *p_slotpos;
    unsigned int *p_mask;
    GETSYM(p_xn, g_xn); GETSYM(p_all, g_all);
    GETSYM(p_qh, g_qh); GETSYM(p_kh, g_kh); GETSYM(p_vh, g_vh);
    GETSYM(p_av, g_av); GETSYM(p_x1, g_x1);
    GETSYM(p_x2n, g_x2n); GETSYM(p_x2f, g_x2f);
    GETSYM(p_probs, g_probs); GETSYM(p_topE, g_topE); GETSYM(p_topG, g_topG);
    GETSYM(p_counts, g_counts); GETSYM(p_segoff, g_segoff);
    GETSYM(p_rowmap, g_rowmap); GETSYM(p_slotpos, g_slotpos);
    GETSYM(p_mid, g_mid); GETSYM(p_y, g_yy); GETSYM(p_mask, g_mask);
    GETSYM(p_woc, g_woc); GETSYM(p_wall, g_wall);

    cudaFuncSetAttribute(tgemm<0>, cudaFuncAttributeMaxDynamicSharedMemorySize, TG_SMEM_BYTES);
    cudaFuncSetAttribute(tgemm<1>, cudaFuncAttributeMaxDynamicSharedMemorySize, TG_SMEM_BYTES);

    // 0. pack small weights (tf32-rounded); w1/w2 convert inside the MoE GEMMs
    {
        int m4 = DMODEL * DMODEL / 4;
        round4_kernel<<<(m4 + 255) / 256, 256>>>((const float4*)wo, (float4*)p_woc, m4);
        pack_all_kernel<<<(DMODEL * NALL + 255) / 256, 256>>>(
            wq, wk, wv, wq_idx, wk_idx, w_head, p_wall);
    }

    // 1. norm1
    rmsnorm_kernel<<<TSEQ, 256>>>(x, norm1_w, p_xn, nullptr);

    // 2. single fused projection GEMM (qkv + indexer, N=3396)
    tgemm<0><<<dim3((NALL + 127) / 128, 16, 1), 256, TG_SMEM_BYTES>>>(
        p_xn, DMODEL, nullptr, p_wall, 0, nullptr, 0,
        nullptr, p_all, NALL, nullptr, TSEQ, NALL, DMODEL, 0);

    // 3. indexer scores + fused top-512 mask
    idx_kernel<<<dim3(32, 32), 256>>>(p_all, idxout);
    topk_mask_kernel<<<TSEQ, 512>>>(idxout, p_mask);

    // 4. rope + transpose
    rope_kernel<<<(TSEQ * DMODEL) / 256, 256>>>(p_all, p_qh, p_kh, p_vh);

    // 5. dense masked flash attention (128-row q tiles, heavy first)
    attn_flash<<<dim3(TSEQ / 128, NHEAD), 256>>>(p_qh, p_kh, p_vh, p_mask, p_av);

    // 6. output projection + residual
    tgemm<0><<<dim3(8, 16, 1), 256, TG_SMEM_BYTES>>>(p_av, DMODEL, nullptr, p_woc, 0, nullptr, 0,
        x, p_x1, DMODEL, nullptr, TSEQ, DMODEL, DMODEL, 0);

    // 7. norm2 + router + grouping + aux
    rmsnorm_kernel<<<TSEQ, 256>>>(p_x1, norm2_w, p_x2n, p_x2f);
    router_kernel<<<TSEQ, 256>>>(p_x2f, router_w, router_b, p_probs, p_topE, p_topG);
    group_kernel<<<1, 256>>>(p_topE, p_counts, p_segoff, p_rowmap, p_slotpos);
    aux_kernel<<<1, 256>>>(p_probs, p_counts, auxp);

    // 8. MoE grouped GEMMs (raw weights, tf32 cvt at fragment load)
    tgemm<1><<<dim3(DFFN / 128, 16, NEXP), 256, TG_SMEM_BYTES>>>(
        p_x2n, DMODEL, p_rowmap, w1, (long long)DMODEL * DFFN, b1, DFFN,
        nullptr, p_mid, DFFN, p_segoff, 0, DFFN, DMODEL, 1);
    tgemm<1><<<dim3(DMODEL / 128, 16, NEXP), 256, TG_SMEM_BYTES>>>(
        p_mid, DFFN, nullptr, w2, (long long)DFFN * DMODEL, b2, DMODEL,
        nullptr, p_y, DMODEL, p_segoff, 0, DMODEL, DFFN, 0);

    // 9. combine
    combine_kernel<<<(TSEQ * DMODEL / 4) / 256, 256>>>(p_x1, p_y, p_slotpos, p_topG, out);
}

// round 11
// speedup vs baseline: 1.2063x; 1.0657x over previous
#include <cuda_runtime.h>
#include <math.h>
#include <stdint.h>

// ---------------- constants ----------------
static const int TSEQ = 2048;
static const int DMODEL = 1024;
static const int NHEAD = 16;
static const int HDIM = 64;
static const int DFFN = 4096;
static const int NEXP = 8;
static const int HIDX = 4;
static const int DIDX = 64;
static const int KSEL = 512;
static const int NALL = 3 * DMODEL + HIDX * DIDX + DIDX + HIDX;  // 3396
static const int OFF_Q = 0;
static const int OFF_K = DMODEL;
static const int OFF_V = 2 * DMODEL;
static const int OFF_QI = 3 * DMODEL;           // 3072
static const int OFF_KI = OFF_QI + HIDX * DIDX; // 3328
static const int OFF_HW = OFF_KI + DIDX;        // 3392
static const int PACK_BLOCKS = (DMODEL * NALL) / 256;     // 13584 (exact)
static const int WO4_BLOCKS = (DMODEL * DMODEL / 4) / 256; // 1024

// ---------------- device scratch ----------------
__device__ float g_xn[TSEQ * DMODEL];
__device__ float g_all[TSEQ * NALL];
__device__ float g_qh[TSEQ * DMODEL];
__device__ float g_kh[TSEQ * DMODEL];
__device__ float g_vh[TSEQ * DMODEL];
__device__ float g_av[TSEQ * DMODEL];
__device__ float g_x1[TSEQ * DMODEL];
__device__ float g_x2n[TSEQ * DMODEL];   // tf32-rounded
__device__ float g_x2f[TSEQ * DMODEL];   // full fp32 (router)
__device__ float g_probs[TSEQ * NEXP];
__device__ int   g_topE[TSEQ * 2];
__device__ float g_topG[TSEQ * 2];
__device__ int   g_counts[NEXP];
__device__ int   g_segoff[NEXP + 1];
__device__ int   g_rowmap[TSEQ * 2];
__device__ int   g_slotpos[TSEQ * 2];
__device__ float g_mid[(size_t)(TSEQ * 2) * DFFN];
__device__ float g_yy[(size_t)(TSEQ * 2) * DMODEL];
__device__ unsigned int g_mask[TSEQ * (TSEQ / 32)];
__device__ float g_woc[DMODEL * DMODEL];
__device__ float g_wall[DMODEL * NALL];

// ---------------- helpers ----------------
__device__ __forceinline__ float gelu_tanh(float x) {
    float x3 = x * x * x;
    float u = 0.7978845608028654f * (x + 0.044715f * x3);
    return 0.5f * x * (1.0f + tanhf(u));
}

__device__ __forceinline__ unsigned int fmono(float f) {
    unsigned int u = __float_as_uint(f);
    return (u & 0x80000000u) ? ~u : (u | 0x80000000u);
}

__device__ __forceinline__ uint32_t f2tf32(float f) {
    uint32_t r;
    asm("cvt.rna.tf32.f32 %0, %1;" : "=r"(r) : "f"(f));
    return r;
}
__device__ __forceinline__ float rtf(float f) { return __uint_as_float(f2tf32(f)); }

__device__ __forceinline__ void cp16(uint32_t dst, const float* src, int sz) {
    asm volatile("cp.async.cg.shared.global [%0], [%1], 16, %2;" :: "r"(dst), "l"(src), "r"(sz));
}

__device__ __forceinline__ void mma_tf32(float* c, const uint32_t* a, const uint32_t* b) {
    asm volatile(
        "mma.sync.aligned.m16n8k8.row.col.f32.tf32.tf32.f32 "
        "{%0,%1,%2,%3}, {%4,%5,%6,%7}, {%8,%9}, {%0,%1,%2,%3};"
        : "+f"(c[0]), "+f"(c[1]), "+f"(c[2]), "+f"(c[3])
        : "r"(a[0]), "r"(a[1]), "r"(a[2]), "r"(a[3]), "r"(b[0]), "r"(b[1]));
}

// ---------------- fused prep: rmsnorm1 | pack_all | round4(wo) ----------------
__global__ __launch_bounds__(256) void prep_kernel(
    const float* __restrict__ x, const float* __restrict__ norm1_w, float* __restrict__ xn,
    const float* __restrict__ wq, const float* __restrict__ wk, const float* __restrict__ wv,
    const float* __restrict__ wq_idx, const float* __restrict__ wk_idx,
    const float* __restrict__ w_head, float* __restrict__ wall,
    const float* __restrict__ wo, float* __restrict__ woc)
{
    int b = blockIdx.x, tid = threadIdx.x;
    if (b < TSEQ) {
        // rmsnorm (rounded output)
        __shared__ float red[256];
        const float* xr = x + (size_t)b * DMODEL;
        float s = 0.f;
        for (int d = tid; d < DMODEL; d += 256) { float v = xr[d]; s += v * v; }
        red[tid] = s; __syncthreads();
        for (int o = 128; o > 0; o >>= 1) { if (tid < o) red[tid] += red[tid + o]; __syncthreads(); }
        float rms = rsqrtf(red[0] / (float)DMODEL + 1e-6f);
        float* yr = xn + (size_t)b * DMODEL;
        for (int d = tid; d < DMODEL; d += 256) yr[d] = rtf(xr[d] * rms * norm1_w[d]);
    } else if (b < TSEQ + PACK_BLOCKS) {
        int i = (b - TSEQ) * 256 + tid;
        int d = i / NALL, j = i - d * NALL;
        float v;
        if (j < OFF_K)        v = wq[d * DMODEL + j];
        else if (j < OFF_V)   v = wk[d * DMODEL + (j - OFF_K)];
        else if (j < OFF_QI)  v = wv[d * DMODEL + (j - OFF_V)];
        else if (j < OFF_KI)  v = wq_idx[d * (HIDX * DIDX) + (j - OFF_QI)];
        else if (j < OFF_HW)  v = wk_idx[d * DIDX + (j - OFF_KI)];
        else                  v = w_head[d * HIDX + (j - OFF_HW)];
        wall[i] = rtf(v);
    } else {
        int i = (b - TSEQ - PACK_BLOCKS) * 256 + tid;
        float4 v = ((const float4*)wo)[i];
        v.x = rtf(v.x); v.y = rtf(v.y); v.z = rtf(v.z); v.w = rtf(v.w);
        ((float4*)woc)[i] = v;
    }
}

// ---------------- unified tf32 tensor GEMM (TBM=128, 3-stage, 2 CTA/SM) ----------------
#define BKM 128
#define BKK 32
#define LDA_S 36
#define LDB_S 132
#define A_STAGE (BKM * LDA_S)
#define B_STAGE (BKK * LDB_S)
#define STAGE_FLOATS (A_STAGE + B_STAGE)
#define NSTAGE 3
#define TG_SMEM_BYTES (NSTAGE * STAGE_FLOATS * 4)

extern __shared__ float smem_dyn[];

template <int CVTB>
__global__ void __launch_bounds__(256, 2) tgemm(
    const float* __restrict__ A, int lda,
    const int* __restrict__ rowmap,
    const float* __restrict__ Bbase, long long strideB,
    const float* __restrict__ biasBase, int biasStride,
    const float* __restrict__ residual,
    float* __restrict__ C, int ldc,
    const int* __restrict__ segoff,
    int M, int N, int K, int doGelu)
{
    int e = blockIdx.z;
    int s0 = 0, nrows = M;
    if (segoff) { s0 = segoff[e]; nrows = segoff[e + 1] - s0; }
    int rowTile = blockIdx.y;
    if (rowTile * BKM >= nrows) return;
    int colStart = blockIdx.x * 128;
    const float* B = Bbase + (long long)e * strideB;

    int tid = threadIdx.x;
    int warpId = tid >> 5, lane = tid & 31;
    int grp = lane >> 2, tig = lane & 3;
    int wm = (warpId >> 2) * 64;
    int wn = (warpId & 3) * 32;

    uint32_t sbase = (uint32_t)__cvta_generic_to_shared(smem_dyn);

    const float* aSrc[4]; int aSz[4]; uint32_t aDst[4];
    const float* bSrc[4]; int bSz[4]; uint32_t bDst[4];
#pragma unroll
    for (int i = 0; i < 4; i++) {
        int c = tid + i * 256;
        int arow = c >> 3, akc = (c & 7) * 4;
        int lrow = rowTile * BKM + arow;
        bool v = lrow < nrows;
        int gidx = 0;
        if (v) {
            int base = s0 + lrow;
            gidx = rowmap ? rowmap[base] : base;
        }
        aSrc[i] = A + (size_t)gidx * lda + akc;
        aSz[i] = v ? 16 : 0;
        aDst[i] = (uint32_t)((arow * LDA_S + akc) * 4);

        int brow = c >> 5, bnc = (c & 31) * 4;
        int col = colStart + bnc;
        bool bv = (col + 4 <= N);
        bSz[i] = bv ? 16 : 0;
        bSrc[i] = B + (size_t)brow * N + (bv ? col : 0);
        bDst[i] = (uint32_t)((A_STAGE + brow * LDB_S + bnc) * 4);
    }

    float acc[4][4][4];
#pragma unroll
    for (int mi = 0; mi < 4; mi++)
#pragma unroll
        for (int ni = 0; ni < 4; ni++)
#pragma unroll
            for (int q = 0; q < 4; q++) acc[mi][ni][q] = 0.f;

    int KT = K / BKK;

#pragma unroll
    for (int p = 0; p < NSTAGE - 1; p++) {
        if (p < KT) {
            int k0 = p * BKK;
            uint32_t sb = sbase + (uint32_t)((p % NSTAGE) * STAGE_FLOATS * 4);
#pragma unroll
            for (int i = 0; i < 4; i++) cp16(sb + aDst[i], aSrc[i] + k0, aSz[i]);
#pragma unroll
            for (int i = 0; i < 4; i++) cp16(sb + bDst[i], bSrc[i] + (size_t)k0 * N, bSz[i]);
            asm volatile("cp.async.commit_group;");
        }
    }

    for (int it = 0; it < KT; it++) {
        if (it + NSTAGE - 1 < KT) {
            int k0 = (it + NSTAGE - 1) * BKK;
            uint32_t sb = sbase + (uint32_t)(((it + NSTAGE - 1) % NSTAGE) * STAGE_FLOATS * 4);
#pragma unroll
            for (int i = 0; i < 4; i++) cp16(sb + aDst[i], aSrc[i] + k0, aSz[i]);
#pragma unroll
            for (int i = 0; i < 4; i++) cp16(sb + bDst[i], bSrc[i] + (size_t)k0 * N, bSz[i]);
            asm volatile("cp.async.commit_group;");
        }
        int pend = KT - 1 - it;
        if (pend > NSTAGE - 1) pend = NSTAGE - 1;
        if (pend >= 2)      asm volatile("cp.async.wait_group 2;");
        else if (pend == 1) asm volatile("cp.async.wait_group 1;");
        else                asm volatile("cp.async.wait_group 0;");
        __syncthreads();

        const uint32_t* Ab = (const uint32_t*)(smem_dyn + (size_t)(it % NSTAGE) * STAGE_FLOATS);
        const uint32_t* Bb = Ab + A_STAGE;
#pragma unroll
        for (int ks = 0; ks < 4; ks++) {
            int kb = ks * 8;
            uint32_t af[4][4];
#pragma unroll
            for (int mi = 0; mi < 4; mi++) {
                int r = wm + mi * 16 + grp;
                af[mi][0] = Ab[r * LDA_S + kb + tig];
                af[mi][1] = Ab[(r + 8) * LDA_S + kb + tig];
                af[mi][2] = Ab[r * LDA_S + kb + tig + 4];
                af[mi][3] = Ab[(r + 8) * LDA_S + kb + tig + 4];
            }
            uint32_t bf[4][2];
#pragma unroll
            for (int ni = 0; ni < 4; ni++) {
                int ccol = wn + ni * 8 + grp;
                uint32_t r0 = Bb[(kb + tig) * LDB_S + ccol];
                uint32_t r1 = Bb[(kb + tig + 4) * LDB_S + ccol];
                if (CVTB) {
                    bf[ni][0] = f2tf32(__uint_as_float(r0));
                    bf[ni][1] = f2tf32(__uint_as_float(r1));
                } else {
                    bf[ni][0] = r0;
                    bf[ni][1] = r1;
                }
            }
#pragma unroll
            for (int mi = 0; mi < 4; mi++)
#pragma unroll
                for (int ni = 0; ni < 4; ni++)
                    mma_tf32(acc[mi][ni], af[mi], bf[ni]);
        }
        __syncthreads();
    }

    const float* bias = biasBase ? (biasBase + (long long)e * biasStride) : nullptr;
#pragma unroll
    for (int mi = 0; mi < 4; mi++) {
        int rbase = wm + mi * 16 + grp;
#pragma unroll
        for (int half = 0; half < 2; half++) {
            int r = rbase + half * 8;
            int lrow = rowTile * BKM + r;
            if (lrow >= nrows) continue;
            int grow = s0 + lrow;
#pragma unroll
            for (int ni = 0; ni < 4; ni++) {
                int col = colStart + wn + ni * 8 + tig * 2;
                float v0 = acc[mi][ni][half * 2 + 0];
                float v1 = acc[mi][ni][half * 2 + 1];
                if (bias) { v0 += bias[col]; v1 += bias[col + 1]; }
                if (doGelu) {
                    v0 = rtf(gelu_tanh(v0));
                    v1 = rtf(gelu_tanh(v1));
                }
                if (residual) {
                    v0 += residual[(size_t)grow * ldc + col];
                    v1 += residual[(size_t)grow * ldc + col + 1];
                }
                if (col < N)     C[(size_t)grow * ldc + col] = v0;
                if (col + 1 < N) C[(size_t)grow * ldc + col + 1] = v1;
            }
        }
    }
}

// ---------------- rmsnorm (rounded main output; optional full-precision copy) ----------------
__global__ __launch_bounds__(256) void rmsnorm_kernel(
    const float* __restrict__ x, const float* __restrict__ w,
    float* __restrict__ y, float* __restrict__ yfull)
{
    int t = blockIdx.x, tid = threadIdx.x;
    __shared__ float red[256];
    const float* xr = x + (size_t)t * DMODEL;
    float s = 0.f;
    for (int d = tid; d < DMODEL; d += 256) { float v = xr[d]; s += v * v; }
    red[tid] = s; __syncthreads();
    for (int o = 128; o > 0; o >>= 1) { if (tid < o) red[tid] += red[tid + o]; __syncthreads(); }
    float rms = rsqrtf(red[0] / (float)DMODEL + 1e-6f);
    float* yr = y + (size_t)t * DMODEL;
    for (int d = tid; d < DMODEL; d += 256) {
        float v = xr[d] * rms * w[d];
        yr[d] = rtf(v);
        if (yfull) yfull[(size_t)t * DMODEL + d] = v;
    }
}

// ---------------- fused idx scores | rope (block-range dispatch, 256 thr both) ----------------
__global__ __launch_bounds__(256) void idx_rope_kernel(
    const float* __restrict__ proj, float* __restrict__ out,
    float* __restrict__ qh, float* __restrict__ kh, float* __restrict__ vh)
{
    __shared__ float qshT[64][68];
    __shared__ float kshT[64][68];
    __shared__ float hsh[64][4];
    int tid = threadIdx.x;

    if (blockIdx.x < 1024) {
        // ---- indexer scores ----
        int t0 = (blockIdx.x >> 5) * 64, s0 = (blockIdx.x & 31) * 64;
        const int tr = (tid >> 4) * 4, tc = (tid & 15) * 4;

        hsh[tid >> 2][tid & 3] = proj[(size_t)(t0 + (tid >> 2)) * NALL + OFF_HW + (tid & 3)];
        for (int i = tid; i < 4096; i += 256) {
            int r = i >> 6, c = i & 63;
            kshT[c][r] = proj[(size_t)(s0 + r) * NALL + OFF_KI + c];
        }
        float acc[4][4];
#pragma unroll
        for (int i = 0; i < 4; i++)
#pragma unroll
            for (int j = 0; j < 4; j++) acc[i][j] = 0.f;

        for (int h = 0; h < HIDX; h++) {
            __syncthreads();
            for (int i = tid; i < 4096; i += 256) {
                int r = i >> 6, c = i & 63;
                qshT[c][r] = proj[(size_t)(t0 + r) * NALL + OFF_QI + h * DIDX + c];
            }
            __syncthreads();
            float dot[4][4];
#pragma unroll
            for (int i = 0; i < 4; i++)
#pragma unroll
                for (int j = 0; j < 4; j++) dot[i][j] = 0.f;
            for (int kk = 0; kk < 64; kk++) {
                float4 a4 = *(const float4*)&qshT[kk][tr];
                float4 b4 = *(const float4*)&kshT[kk][tc];
                float a[4] = {a4.x, a4.y, a4.z, a4.w};
                float b[4] = {b4.x, b4.y, b4.z, b4.w};
#pragma unroll
                for (int i = 0; i < 4; i++)
#pragma unroll
                    for (int j = 0; j < 4; j++) dot[i][j] += a[i] * b[j];
            }
#pragma unroll
            for (int i = 0; i < 4; i++)
#pragma unroll
                for (int j = 0; j < 4; j++)
                    acc[i][j] += hsh[tr + i][h] * fmaxf(dot[i][j], 0.f);
        }
#pragma unroll
        for (int i = 0; i < 4; i++)
#pragma unroll
            for (int j = 0; j < 4; j++)
                out[(size_t)(t0 + tr + i) * TSEQ + (s0 + tc + j)] = acc[i][j] * 0.125f;
    } else {
        // ---- rope + transpose (rounds outputs) ----
        int idx = (blockIdx.x - 1024) * 256 + tid;
        int t = idx >> 10;
        int hd = idx & 1023;
        int h = hd >> 6, d = hd & 63;
        int j = d & 31;
        double invd = exp(-((double)(2 * j) / 64.0) * log(10000.0));
        float ang = (float)((double)t * invd);
        float c = cosf(ang), s = sinf(ang);
        const float* row = proj + (size_t)t * NALL;
        float q = row[OFF_Q + hd], k = row[OFF_K + hd], v = row[OFF_V + hd];
        float qr, kr;
        if (d < 32) {
            qr = q * c - row[OFF_Q + hd + 32] * s;
            kr = k * c - row[OFF_K + hd + 32] * s;
        } else {
            qr = q * c + row[OFF_Q + hd - 32] * s;
            kr = k * c + row[OFF_K + hd - 32] * s;
        }
        int o = ((h * TSEQ) + t) * HDIM + d;
        qh[o] = rtf(qr); kh[o] = rtf(kr); vh[o] = rtf(v);
    }
}

// ---------------- fused top-512 radix-select + mask build ----------------
__global__ __launch_bounds__(512) void topk_mask_kernel(
    const float* __restrict__ idxs, unsigned int* __restrict__ mask)
{
    __shared__ unsigned long long keys[2048];
    __shared__ unsigned int hist[256];
    __shared__ unsigned int sh_k;
    __shared__ unsigned long long sh_prefix;

    int t = blockIdx.x, tid = threadIdx.x;

    for (int i = tid; i < 2048; i += 512) {
        unsigned long long kk = 0ull;
        if (i <= t) {
            float v = idxs[(size_t)t * TSEQ + i];
            kk = ((unsigned long long)fmono(v) << 32) | (unsigned int)(2047 - i);
        }
        keys[i] = kk;
    }
    if (tid == 0) { sh_k = (unsigned int)KSEL; sh_prefix = 0ull; }
    __syncthreads();

    const int shifts[6] = {56, 48, 40, 32, 8, 0};
    unsigned long long prefix_mask = 0ull;
#pragma unroll
    for (int p = 0; p < 6; p++) {
        int shift = shifts[p];
        if (tid < 256) hist[tid] = 0u;
        __syncthreads();
        unsigned long long pref = sh_prefix;
        for (int i = tid; i < 2048; i += 512) {
            unsigned long long key = keys[i];
            if ((key & prefix_mask) == pref)
                atomicAdd(&hist[(unsigned int)(key >> shift) & 255u], 1u);
        }
        __syncthreads();
        for (int off = 1; off < 256; off <<= 1) {
            unsigned int add = 0u;
            if (tid < 256 && tid + off < 256) add = hist[tid + off];
            __syncthreads();
            if (tid < 256) hist[tid] += add;
            __syncthreads();
        }
        unsigned int k = sh_k;
        if (tid < 256) {
            unsigned int s_here = hist[tid];
            unsigned int s_next = (tid == 255) ? 0u : hist[tid + 1];
            if (s_here >= k && s_next < k) {
                sh_prefix = pref | ((unsigned long long)tid << shift);
                sh_k = k - s_next;
            }
        }
        __syncthreads();
        prefix_mask |= (0xFFull << shift);
    }

    unsigned long long thr = sh_prefix;
    int lane = tid & 31, w = tid >> 5;
    for (int word = w; word < 64; word += 16) {
        int i = word * 32 + lane;
        bool sel = (i <= t) && (keys[i] >= thr);
        unsigned int bal = __ballot_sync(0xFFFFFFFFu, sel);
        if (lane == 0) mask[t * 64 + word] = bal;
    }
}

// ---------------- dense masked flash attention (register softmax) ----------------
// grid (TSEQ/128, NHEAD), 256 thr = 8 warps; warp w owns rows [w*16, w*16+16) fully.
__global__ void __launch_bounds__(256, 2) attn_flash(
    const float* __restrict__ qh, const float* __restrict__ kh, const float* __restrict__ vh,
    const unsigned int* __restrict__ mask, float* __restrict__ av)
{
    __shared__ float Ks[64][68];
    __shared__ float Vs[64][68];
    __shared__ float Ps[128][68];

    int qt = gridDim.x - 1 - blockIdx.x, h = blockIdx.y;
    int t0 = qt * 128;
    int tid = threadIdx.x;
    int warpId = tid >> 5, lane = tid & 31;
    int grp = lane >> 2, tig = lane & 3;
    int wm = warpId * 16;
    int r0 = wm + grp, r1 = wm + grp + 8;

    const float* Q0 = qh + ((size_t)h * TSEQ + t0) * HDIM;
    uint32_t qf[8][4];
#pragma unroll
    for (int ks = 0; ks < 8; ks++) {
        int kb = ks * 8;
        qf[ks][0] = __float_as_uint(Q0[r0 * HDIM + kb + tig]);
        qf[ks][1] = __float_as_uint(Q0[r1 * HDIM + kb + tig]);
        qf[ks][2] = __float_as_uint(Q0[r0 * HDIM + kb + tig + 4]);
        qf[ks][3] = __float_as_uint(Q0[r1 * HDIM + kb + tig + 4]);
    }

    float rowM0 = -INFINITY, rowM1 = -INFINITY;
    float rowL0 = 0.f, rowL1 = 0.f;

    float oacc[8][4];
#pragma unroll
    for (int ni = 0; ni < 8; ni++)
#pragma unroll
        for (int q = 0; q < 4; q++) oacc[ni][q] = 0.f;

    const float* Kb = kh + (size_t)h * TSEQ * HDIM;
    const float* Vb = vh + (size_t)h * TSEQ * HDIM;

    int ktMax = 2 * qt + 1;
    for (int kt = 0; kt <= ktMax; kt++) {
        __syncthreads();   // all warps done reading Ks/Vs from previous tile
        for (int i = tid; i < 1024; i += 256) {
            int row = i >> 4, c4 = (i & 15) * 4;
            *(float4*)&Ks[row][c4] = *(const float4*)(Kb + (size_t)(kt * 64 + row) * HDIM + c4);
            *(float4*)&Vs[row][c4] = *(const float4*)(Vb + (size_t)(kt * 64 + row) * HDIM + c4);
        }
        __syncthreads();

        // S = Q @ K^T : warp covers its 16 rows x full 64 cols
        float sacc[8][4];
#pragma unroll
        for (int ni = 0; ni < 8; ni++)
#pragma unroll
            for (int q = 0; q < 4; q++) sacc[ni][q] = 0.f;
#pragma unroll
        for (int ks = 0; ks < 8; ks++) {
            int kb = ks * 8;
#pragma unroll
            for (int ni = 0; ni < 8; ni++) {
                int n = ni * 8 + grp;
                uint32_t bf[2];
                bf[0] = __float_as_uint(Ks[n][kb + tig]);
                bf[1] = __float_as_uint(Ks[n][kb + tig + 4]);
                mma_tf32(sacc[ni], qf[ks], bf);
            }
        }

        // mask + scale in registers
        unsigned int mw0[2], mw1[2];
        mw0[0] = mask[(t0 + r0) * 64 + kt * 2];
        mw0[1] = mask[(t0 + r0) * 64 + kt * 2 + 1];
        mw1[0] = mask[(t0 + r1) * 64 + kt * 2];
        mw1[1] = mask[(t0 + r1) * 64 + kt * 2 + 1];
#pragma unroll
        for (int ni = 0; ni < 8; ni++) {
            int c = ni * 8 + tig * 2;
            int wsel = c >> 5, b = c & 31;
            sacc[ni][0] = ((mw0[wsel] >> b) & 1u)       ? sacc[ni][0] * 0.125f : -INFINITY;
            sacc[ni][1] = ((mw0[wsel] >> (b + 1)) & 1u) ? sacc[ni][1] * 0.125f : -INFINITY;
            sacc[ni][2] = ((mw1[wsel] >> b) & 1u)       ? sacc[ni][2] * 0.125f : -INFINITY;
            sacc[ni][3] = ((mw1[wsel] >> (b + 1)) & 1u) ? sacc[ni][3] * 0.125f : -INFINITY;
        }

        // row max via quad shuffles (exact: max is order-free)
        float tmax0 = -INFINITY, tmax1 = -INFINITY;
#pragma unroll
        for (int ni = 0; ni < 8; ni++) {
            tmax0 = fmaxf(tmax0, fmaxf(sacc[ni][0], sacc[ni][1]));
            tmax1 = fmaxf(tmax1, fmaxf(sacc[ni][2], sacc[ni][3]));
        }
        tmax0 = fmaxf(tmax0, __shfl_xor_sync(0xFFFFFFFFu, tmax0, 1));
        tmax0 = fmaxf(tmax0, __shfl_xor_sync(0xFFFFFFFFu, tmax0, 2));
        tmax1 = fmaxf(tmax1, __shfl_xor_sync(0xFFFFFFFFu, tmax1, 1));
        tmax1 = fmaxf(tmax1, __shfl_xor_sync(0xFFFFFFFFu, tmax1, 2));

        float mnew0 = fmaxf(rowM0, tmax0), mnew1 = fmaxf(rowM1, tmax1);
        bool inval0 = (mnew0 == -INFINITY), inval1 = (mnew1 == -INFINITY);

        float tsum0 = 0.f, tsum1 = 0.f;
#pragma unroll
        for (int ni = 0; ni < 8; ni++) {
            int c = ni * 8 + tig * 2;
            float p00 = inval0 ? 0.f : expf(sacc[ni][0] - mnew0);
            float p01 = inval0 ? 0.f : expf(sacc[ni][1] - mnew0);
            float p10 = inval1 ? 0.f : expf(sacc[ni][2] - mnew1);
            float p11 = inval1 ? 0.f : expf(sacc[ni][3] - mnew1);
            Ps[r0][c]     = rtf(p00);
            Ps[r0][c + 1] = rtf(p01);
            Ps[r1][c]     = rtf(p10);
            Ps[r1][c + 1] = rtf(p11);
            tsum0 += p00; tsum0 += p01;
            tsum1 += p10; tsum1 += p11;
        }
        tsum0 += __shfl_xor_sync(0xFFFFFFFFu, tsum0, 1);
        tsum0 += __shfl_xor_sync(0xFFFFFFFFu, tsum0, 2);
        tsum1 += __shfl_xor_sync(0xFFFFFFFFu, tsum1, 1);
        tsum1 += __shfl_xor_sync(0xFFFFFFFFu, tsum1, 2);

        float sc0 = inval0 ? 1.f : expf(rowM0 - mnew0);
        float sc1 = inval1 ? 1.f : expf(rowM1 - mnew1);
        rowM0 = mnew0; rowM1 = mnew1;
        rowL0 = rowL0 * sc0 + tsum0;
        rowL1 = rowL1 * sc1 + tsum1;

#pragma unroll
        for (int ni = 0; ni < 8; ni++) {
            oacc[ni][0] *= sc0; oacc[ni][1] *= sc0;
            oacc[ni][2] *= sc1; oacc[ni][3] *= sc1;
        }
        __syncwarp();   // Ps rows owned by this warp; order writes before reads

#pragma unroll
        for (int ks = 0; ks < 8; ks++) {
            int kb = ks * 8;
            uint32_t pa[4];
            pa[0] = __float_as_uint(Ps[r0][kb + tig]);
            pa[1] = __float_as_uint(Ps[r1][kb + tig]);
            pa[2] = __float_as_uint(Ps[r0][kb + tig + 4]);
            pa[3] = __float_as_uint(Ps[r1][kb + tig + 4]);
#pragma unroll
            for (int ni = 0; ni < 8; ni++) {
                int n = ni * 8 + grp;
                uint32_t vf[2];
                vf[0] = __float_as_uint(Vs[kb + tig][n]);
                vf[1] = __float_as_uint(Vs[kb + tig + 4][n]);
                mma_tf32(oacc[ni], pa, vf);
            }
        }
    }

    float i0 = 1.f / rowL0;
    float i1 = 1.f / rowL1;
#pragma unroll
    for (int ni = 0; ni < 8; ni++) {
        int c = ni * 8 + tig * 2;
        size_t o0 = (size_t)(t0 + r0) * DMODEL + h * HDIM + c;
        size_t o1 = (size_t)(t0 + r1) * DMODEL + h * HDIM + c;
        av[o0]     = rtf(oacc[ni][0] * i0);
        av[o0 + 1] = rtf(oacc[ni][1] * i0);
        av[o1]     = rtf(oacc[ni][2] * i1);
        av[o1 + 1] = rtf(oacc[ni][3] * i1);
    }
}

// ---------------- router (reads FULL-precision x2n) ----------------
__global__ __launch_bounds__(256) void router_kernel(
    const float* __restrict__ x2n, const float* __restrict__ rw, const float* __restrict__ rb,
    float* __restrict__ probs, int* __restrict__ topE, float* __restrict__ topG)
{
    int t = blockIdx.x, tid = threadIdx.x;
    __shared__ float red[256];
    __shared__ float lg[8];
    float acc[8];
#pragma unroll
    for (int e = 0; e < 8; e++) acc[e] = 0.f;
    const float* xr = x2n + (size_t)t * DMODEL;
    for (int d = tid; d < DMODEL; d += 256) {
        float xv = xr[d];
#pragma unroll
        for (int e = 0; e < 8; e++) acc[e] += xv * rw[(size_t)d * NEXP + e];
    }
    for (int e = 0; e < 8; e++) {
        red[tid] = acc[e]; __syncthreads();
        for (int o = 128; o > 0; o >>= 1) { if (tid < o) red[tid] += red[tid + o]; __syncthreads(); }
        if (tid == 0) lg[e] = red[0] + rb[e];
        __syncthreads();
    }
    if (tid == 0) {
        float m = lg[0];
        for (int e = 1; e < 8; e++) m = fmaxf(m, lg[e]);
        float p[8], s = 0.f;
        for (int e = 0; e < 8; e++) { p[e] = expf(lg[e] - m); s += p[e]; }
        for (int e = 0; e < 8; e++) p[e] /= s;
        int e0 = 0;
        for (int e = 1; e < 8; e++) if (p[e] > p[e0]) e0 = e;
        int e1 = -1;
        for (int e = 0; e < 8; e++) if (e != e0 && (e1 < 0 || p[e] > p[e1])) e1 = e;
        float denom = p[e0] + p[e1];
        for (int e = 0; e < 8; e++) probs[(size_t)t * NEXP + e] = p[e];
        topE[t * 2 + 0] = e0; topE[t * 2 + 1] = e1;
        topG[t * 2 + 0] = p[e0] / denom; topG[t * 2 + 1] = p[e1] / denom;
    }
}

// ---------------- deterministic grouping (warp-ballot scan, order-preserving) ----------------
__global__ __launch_bounds__(256) void group_kernel(
    const int* __restrict__ topE, int* __restrict__ counts,
    int* __restrict__ segoff, int* __restrict__ rowmap,
    int* __restrict__ slotpos)
{
    __shared__ short sE[TSEQ * 2];
    __shared__ int sSeg[NEXP + 1];
    __shared__ int sCnt[NEXP];
    int tid = threadIdx.x;
    int lane = tid & 31, w = tid >> 5;
    for (int i = tid; i < TSEQ * 2; i += 256) sE[i] = (short)topE[i];
    __syncthreads();

    {
        int e = w;
        int c = 0;
        for (int i0 = 0; i0 < TSEQ * 2; i0 += 32) {
            unsigned int m = __ballot_sync(0xFFFFFFFFu, sE[i0 + lane] == e);
            c += __popc(m);
        }
        if (lane == 0) { counts[e] = c; sCnt[e] = c; }
    }
    __syncthreads();
    if (tid == 0) {
        int o = 0;
        for (int i = 0; i < 8; i++) { sSeg[i] = o; segoff[i] = o; o += sCnt[i]; }
        sSeg[8] = o; segoff[8] = o;
    }
    __syncthreads();

    {
        int e = w;
        int pos = sSeg[e];
        unsigned int ltmask = (1u << lane) - 1u;
        for (int i0 = 0; i0 < TSEQ * 2; i0 += 32) {
            int i = i0 + lane;
            bool match = (sE[i] == e);
            unsigned int m = __ballot_sync(0xFFFFFFFFu, match);
            if (match) {
                int off = __popc(m & ltmask);
                rowmap[pos + off] = i >> 1;
                slotpos[i] = pos + off;
            }
            pos += __popc(m);
        }
    }
}

// ---------------- fused combine | aux ----------------
__global__ __launch_bounds__(256) void combine_aux_kernel(
    const float* __restrict__ x1, const float* __restrict__ y,
    const int* __restrict__ slotpos, const float* __restrict__ topG,
    const float* __restrict__ probs, const int* __restrict__ counts,
    float* __restrict__ out, float* __restrict__ outAux)
{
    int tid = threadIdx.x;
    if (blockIdx.x < (TSEQ * DMODEL / 4) / 256) {
        int i4 = blockIdx.x * 256 + tid;
        int t = i4 >> 8, d4 = (i4 & 255) * 4;
        int p0 = slotpos[t * 2 + 0], p1 = slotpos[t * 2 + 1];
        float g0 = topG[t * 2 + 0], g1 = topG[t * 2 + 1];
        float4 a = *(const float4*)(x1 + (size_t)t * DMODEL + d4);
        float4 y0 = *(const float4*)(y + (size_t)p0 * DMODEL + d4);
        float4 y1 = *(const float4*)(y + (size_t)p1 * DMODEL + d4);
        float4 r;
        r.x = a.x + g0 * y0.x + g1 * y1.x;
        r.y = a.y + g0 * y0.y + g1 * y1.y;
        r.z = a.z + g0 * y0.z + g1 * y1.z;
        r.w = a.w + g0 * y0.w + g1 * y1.w;
        *(float4*)(out + (size_t)t * DMODEL + d4) = r;
    } else {
        __shared__ float red[256];
        float a = 0.f;
        for (int e = 0; e < 8; e++) {
            float s = 0.f;
            for (int t = tid; t < TSEQ; t += 256) s += probs[(size_t)t * NEXP + e];
            red[tid] = s; __syncthreads();
            for (int o = 128; o > 0; o >>= 1) { if (tid < o) red[tid] += red[tid + o]; __syncthreads(); }
            if (tid == 0) a += (float)counts[e] * red[0];
            __syncthreads();
        }
        if (tid == 0) *outAux = 8.f * a / ((float)TSEQ * (float)TSEQ);
    }
}

// ---------------- host launch ----------------
#define GETSYM(ptr, sym) do { void* _p_; cudaGetSymbolAddress(&_p_, sym); ptr = (decltype(ptr))_p_; } while (0)

extern "C" void kernel_launch(void* const* d_in, const int* in_sizes, int n_in,
                              void* d_out, int out_size)
{
    const float* x        = (const float*)d_in[0];
    const float* norm1_w  = (const float*)d_in[1];
    const float* norm2_w  = (const float*)d_in[2];
    const float* wq_idx   = (const float*)d_in[3];
    const float* wk_idx   = (const float*)d_in[4];
    const float* w_head   = (const float*)d_in[5];
    const float* wq       = (const float*)d_in[6];
    const float* wk       = (const float*)d_in[7];
    const float* wv       = (const float*)d_in[8];
    const float* wo       = (const float*)d_in[9];
    const float* router_w = (const float*)d_in[10];
    const float* router_b = (const float*)d_in[11];
    const float* w1       = (const float*)d_in[12];
    const float* b1       = (const float*)d_in[13];
    const float* w2       = (const float*)d_in[14];
    const float* b2       = (const float*)d_in[15];

    float* out    = (float*)d_out;
    float* auxp   = out + (size_t)TSEQ * DMODEL;
    float* idxout = auxp + 1;

    float *p_xn, *p_all, *p_qh, *p_kh, *p_vh;
    float *p_av, *p_x1, *p_x2n, *p_x2f, *p_probs, *p_topG, *p_mid, *p_y;
    float *p_woc, *p_wall;
    int *p_topE, *p_counts, *p_segoff, *p_rowmap, *p_slotpos;
    unsigned int *p_mask;
    GETSYM(p_xn, g_xn); GETSYM(p_all, g_all);
    GETSYM(p_qh, g_qh); GETSYM(p_kh, g_kh); GETSYM(p_vh, g_vh);
    GETSYM(p_av, g_av); GETSYM(p_x1, g_x1);
    GETSYM(p_x2n, g_x2n); GETSYM(p_x2f, g_x2f);
    GETSYM(p_probs, g_probs); GETSYM(p_topE, g_topE); GETSYM(p_topG, g_topG);
    GETSYM(p_counts, g_counts); GETSYM(p_segoff, g_segoff);
    GETSYM(p_rowmap, g_rowmap); GETSYM(p_slotpos, g_slotpos);
    GETSYM(p_mid, g_mid); GETSYM(p_y, g_yy); GETSYM(p_mask, g_mask);
    GETSYM(p_woc, g_woc); GETSYM(p_wall, g_wall);

    cudaFuncSetAttribute(tgemm<0>, cudaFuncAttributeMaxDynamicSharedMemorySize, TG_SMEM_BYTES);
    cudaFuncSetAttribute(tgemm<1>, cudaFuncAttributeMaxDynamicSharedMemorySize, TG_SMEM_BYTES);

    // 1. fused prep: rmsnorm1 | pack_all | round4(wo)
    prep_kernel<<<TSEQ + PACK_BLOCKS + WO4_BLOCKS, 256>>>(
        x, norm1_w, p_xn, wq, wk, wv, wq_idx, wk_idx, w_head, p_wall, wo, p_woc);

    // 2. single fused projection GEMM (qkv + indexer, N=3396)
    tgemm<0><<<dim3((NALL + 127) / 128, 16, 1), 256, TG_SMEM_BYTES>>>(
        p_xn, DMODEL, nullptr, p_wall, 0, nullptr, 0,
        nullptr, p_all, NALL, nullptr, TSEQ, NALL, DMODEL, 0);

    // 3. fused indexer scores | rope, then top-512 mask
    idx_rope_kernel<<<1024 + (TSEQ * DMODEL) / 256, 256>>>(p_all, idxout, p_qh, p_kh, p_vh);
    topk_mask_kernel<<<TSEQ, 512>>>(idxout, p_mask);

    // 4. dense masked flash attention (register softmax, heavy tiles first)
    attn_flash<<<dim3(TSEQ / 128, NHEAD), 256>>>(p_qh, p_kh, p_vh, p_mask, p_av);

    // 5. output projection + residual
    tgemm<0><<<dim3(8, 16, 1), 256, TG_SMEM_BYTES>>>(p_av, DMODEL, nullptr, p_woc, 0, nullptr, 0,
        x, p_x1, DMODEL, nullptr, TSEQ, DMODEL, DMODEL, 0);

    // 6. norm2 + router + grouping
    rmsnorm_kernel<<<TSEQ, 256>>>(p_x1, norm2_w, p_x2n, p_x2f);
    router_kernel<<<TSEQ, 256>>>(p_x2f, router_w, router_b, p_probs, p_topE, p_topG);
    group_kernel<<<1, 256>>>(p_topE, p_counts, p_segoff, p_rowmap, p_slotpos);

    // 7. MoE grouped GEMMs (raw weights, tf32 cvt at fragment load)
    tgemm<1><<<dim3(DFFN / 128, 16, NEXP), 256, TG_SMEM_BYTES>>>(
        p_x2n, DMODEL, p_rowmap, w1, (long long)DMODEL * DFFN, b1, DFFN,
        nullptr, p_mid, DFFN, p_segoff, 0, DFFN, DMODEL, 1);
    tgemm<1><<<dim3(DMODEL / 128, 16, NEXP), 256, TG_SMEM_BYTES>>>(
        p_mid, DFFN, nullptr, w2, (long long)DFFN * DMODEL, b2, DMODEL,
        nullptr, p_y, DMODEL, p_segoff, 0, DMODEL, DFFN, 0);

    // 8. fused combine | aux
    combine_aux_kernel<<<(TSEQ * DMODEL / 4) / 256 + 1, 256>>>(
        p_x1, p_y, p_slotpos, p_topG, p_probs, p_counts, out, auxp);
}

// round 13
// speedup vs baseline: 1.2186x; 1.0102x over previous
#include <cuda_runtime.h>
#include <math.h>
#include <stdint.h>

// ---------------- constants ----------------
static const int TSEQ = 2048;
static const int DMODEL = 1024;
static const int NHEAD = 16;
static const int HDIM = 64;
static const int DFFN = 4096;
static const int NEXP = 8;
static const int HIDX = 4;
static const int DIDX = 64;
static const int KSEL = 512;
static const int NALL = 3 * DMODEL + HIDX * DIDX + DIDX + HIDX;  // 3396
static const int OFF_Q = 0;
static const int OFF_K = DMODEL;
static const int OFF_V = 2 * DMODEL;
static const int OFF_QI = 3 * DMODEL;           // 3072
static const int OFF_KI = OFF_QI + HIDX * DIDX; // 3328
static const int OFF_HW = OFF_KI + DIDX;        // 3392
static const int PACK_BLOCKS = (DMODEL * NALL) / 256;      // 13584
static const int WO4_BLOCKS = (DMODEL * DMODEL / 4) / 256; // 1024

// ---------------- device scratch ----------------
__device__ float g_xn[TSEQ * DMODEL];
__device__ float g_all[TSEQ * NALL];
__device__ float g_qh[TSEQ * DMODEL];
__device__ float g_kh[TSEQ * DMODEL];
__device__ float g_vh[TSEQ * DMODEL];
__device__ float g_av[TSEQ * DMODEL];
__device__ float g_x1[TSEQ * DMODEL];
__device__ float g_x2n[TSEQ * DMODEL];   // tf32-rounded (MoE GEMM operand)
__device__ float g_probs[TSEQ * NEXP];
__device__ int   g_topE[TSEQ * 2];
__device__ float g_topG[TSEQ * 2];
__device__ int   g_counts[NEXP];
__device__ int   g_segoff[NEXP + 1];
__device__ int   g_rowmap[TSEQ * 2];
__device__ int   g_slotpos[TSEQ * 2];
__device__ float g_mid[(size_t)(TSEQ * 2) * DFFN];
__device__ float g_yy[(size_t)(TSEQ * 2) * DMODEL];
__device__ unsigned int g_mask[TSEQ * (TSEQ / 32)];
__device__ float g_woc[DMODEL * DMODEL];
__device__ float g_wall[DMODEL * NALL];

// ---------------- helpers ----------------
__device__ __forceinline__ float gelu_tanh(float x) {
    float x3 = x * x * x;
    float u = 0.7978845608028654f * (x + 0.044715f * x3);
    return 0.5f * x * (1.0f + tanhf(u));
}

__device__ __forceinline__ unsigned int fmono(float f) {
    unsigned int u = __float_as_uint(f);
    return (u & 0x80000000u) ? ~u : (u | 0x80000000u);
}

__device__ __forceinline__ uint32_t f2tf32(float f) {
    uint32_t r;
    asm("cvt.rna.tf32.f32 %0, %1;" : "=r"(r) : "f"(f));
    return r;
}
__device__ __forceinline__ float rtf(float f) { return __uint_as_float(f2tf32(f)); }

__device__ __forceinline__ void cp16(uint32_t dst, const float* src, int sz) {
    asm volatile("cp.async.cg.shared.global [%0], [%1], 16, %2;" :: "r"(dst), "l"(src), "r"(sz));
}

__device__ __forceinline__ void mma_tf32(float* c, const uint32_t* a, const uint32_t* b) {
    asm volatile(
        "mma.sync.aligned.m16n8k8.row.col.f32.tf32.tf32.f32 "
        "{%0,%1,%2,%3}, {%4,%5,%6,%7}, {%8,%9}, {%0,%1,%2,%3};"
        : "+f"(c[0]), "+f"(c[1]), "+f"(c[2]), "+f"(c[3])
        : "r"(a[0]), "r"(a[1]), "r"(a[2]), "r"(a[3]), "r"(b[0]), "r"(b[1]));
}

// ---------------- fused prep: rmsnorm1 | pack_all | round4(wo) ----------------
__global__ __launch_bounds__(256) void prep_kernel(
    const float* __restrict__ x, const float* __restrict__ norm1_w, float* __restrict__ xn,
    const float* __restrict__ wq, const float* __restrict__ wk, const float* __restrict__ wv,
    const float* __restrict__ wq_idx, const float* __restrict__ wk_idx,
    const float* __restrict__ w_head, float* __restrict__ wall,
    const float* __restrict__ wo, float* __restrict__ woc)
{
    int b = blockIdx.x, tid = threadIdx.x;
    if (b < TSEQ) {
        __shared__ float red[256];
        const float* xr = x + (size_t)b * DMODEL;
        float s = 0.f;
        for (int d = tid; d < DMODEL; d += 256) { float v = xr[d]; s += v * v; }
        red[tid] = s; __syncthreads();
        for (int o = 128; o > 0; o >>= 1) { if (tid < o) red[tid] += red[tid + o]; __syncthreads(); }
        float rms = rsqrtf(red[0] / (float)DMODEL + 1e-6f);
        float* yr = xn + (size_t)b * DMODEL;
        for (int d = tid; d < DMODEL; d += 256) yr[d] = rtf(xr[d] * rms * norm1_w[d]);
    } else if (b < TSEQ + PACK_BLOCKS) {
        int i = (b - TSEQ) * 256 + tid;
        int d = i / NALL, j = i - d * NALL;
        float v;
        if (j < OFF_K)        v = wq[d * DMODEL + j];
        else if (j < OFF_V)   v = wk[d * DMODEL + (j - OFF_K)];
        else if (j < OFF_QI)  v = wv[d * DMODEL + (j - OFF_V)];
        else if (j < OFF_KI)  v = wq_idx[d * (HIDX * DIDX) + (j - OFF_QI)];
        else if (j < OFF_HW)  v = wk_idx[d * DIDX + (j - OFF_KI)];
        else                  v = w_head[d * HIDX + (j - OFF_HW)];
        wall[i] = rtf(v);
    } else {
        int i = (b - TSEQ - PACK_BLOCKS) * 256 + tid;
        float4 v = ((const float4*)wo)[i];
        v.x = rtf(v.x); v.y = rtf(v.y); v.z = rtf(v.z); v.w = rtf(v.w);
        ((float4*)woc)[i] = v;
    }
}

// ---------------- unified tf32 tensor GEMM (TBM=128, 3-stage, 2 CTA/SM) ----------------
#define BKM 128
#define BKK 32
#define LDA_S 36
#define LDB_S 132
#define A_STAGE (BKM * LDA_S)
#define B_STAGE (BKK * LDB_S)
#define STAGE_FLOATS (A_STAGE + B_STAGE)
#define NSTAGE 3
#define TG_SMEM_BYTES (NSTAGE * STAGE_FLOATS * 4)

extern __shared__ float smem_dyn[];

template <int CVTB>
__global__ void __launch_bounds__(256, 2) tgemm(
    const float* __restrict__ A, int lda,
    const int* __restrict__ rowmap,
    const float* __restrict__ Bbase, long long strideB,
    const float* __restrict__ biasBase, int biasStride,
    const float* __restrict__ residual,
    float* __restrict__ C, int ldc,
    const int* __restrict__ segoff,
    int M, int N, int K, int doGelu)
{
    int e = blockIdx.z;
    int s0 = 0, nrows = M;
    if (segoff) { s0 = segoff[e]; nrows = segoff[e + 1] - s0; }
    int rowTile = blockIdx.y;
    if (rowTile * BKM >= nrows) return;
    int colStart = blockIdx.x * 128;
    const float* B = Bbase + (long long)e * strideB;

    int tid = threadIdx.x;
    int warpId = tid >> 5, lane = tid & 31;
    int grp = lane >> 2, tig = lane & 3;
    int wm = (warpId >> 2) * 64;
    int wn = (warpId & 3) * 32;

    uint32_t sbase = (uint32_t)__cvta_generic_to_shared(smem_dyn);

    const float* aSrc[4]; int aSz[4]; uint32_t aDst[4];
    const float* bSrc[4]; int bSz[4]; uint32_t bDst[4];
#pragma unroll
    for (int i = 0; i < 4; i++) {
        int c = tid + i * 256;
        int arow = c >> 3, akc = (c & 7) * 4;
        int lrow = rowTile * BKM + arow;
        bool v = lrow < nrows;
        int gidx = 0;
        if (v) {
            int base = s0 + lrow;
            gidx = rowmap ? rowmap[base] : base;
        }
        aSrc[i] = A + (size_t)gidx * lda + akc;
        aSz[i] = v ? 16 : 0;
        aDst[i] = (uint32_t)((arow * LDA_S + akc) * 4);

        int brow = c >> 5, bnc = (c & 31) * 4;
        int col = colStart + bnc;
        bool bv = (col + 4 <= N);
        bSz[i] = bv ? 16 : 0;
        bSrc[i] = B + (size_t)brow * N + (bv ? col : 0);
        bDst[i] = (uint32_t)((A_STAGE + brow * LDB_S + bnc) * 4);
    }

    float acc[4][4][4];
#pragma unroll
    for (int mi = 0; mi < 4; mi++)
#pragma unroll
        for (int ni = 0; ni < 4; ni++)
#pragma unroll
            for (int q = 0; q < 4; q++) acc[mi][ni][q] = 0.f;

    int KT = K / BKK;

#pragma unroll
    for (int p = 0; p < NSTAGE - 1; p++) {
        if (p < KT) {
            int k0 = p * BKK;
            uint32_t sb = sbase + (uint32_t)((p % NSTAGE) * STAGE_FLOATS * 4);
#pragma unroll
            for (int i = 0; i < 4; i++) cp16(sb + aDst[i], aSrc[i] + k0, aSz[i]);
#pragma unroll
            for (int i = 0; i < 4; i++) cp16(sb + bDst[i], bSrc[i] + (size_t)k0 * N, bSz[i]);
            asm volatile("cp.async.commit_group;");
        }
    }

    for (int it = 0; it < KT; it++) {
        if (it + NSTAGE - 1 < KT) {
            int k0 = (it + NSTAGE - 1) * BKK;
            uint32_t sb = sbase + (uint32_t)(((it + NSTAGE - 1) % NSTAGE) * STAGE_FLOATS * 4);
#pragma unroll
            for (int i = 0; i < 4; i++) cp16(sb + aDst[i], aSrc[i] + k0, aSz[i]);
#pragma unroll
            for (int i = 0; i < 4; i++) cp16(sb + bDst[i], bSrc[i] + (size_t)k0 * N, bSz[i]);
            asm volatile("cp.async.commit_group;");
        }
        int pend = KT - 1 - it;
        if (pend > NSTAGE - 1) pend = NSTAGE - 1;
        if (pend >= 2)      asm volatile("cp.async.wait_group 2;");
        else if (pend == 1) asm volatile("cp.async.wait_group 1;");
        else                asm volatile("cp.async.wait_group 0;");
        __syncthreads();

        const uint32_t* Ab = (const uint32_t*)(smem_dyn + (size_t)(it % NSTAGE) * STAGE_FLOATS);
        const uint32_t* Bb = Ab + A_STAGE;
#pragma unroll
        for (int ks = 0; ks < 4; ks++) {
            int kb = ks * 8;
            uint32_t af[4][4];
#pragma unroll
            for (int mi = 0; mi < 4; mi++) {
                int r = wm + mi * 16 + grp;
                af[mi][0] = Ab[r * LDA_S + kb + tig];
                af[mi][1] = Ab[(r + 8) * LDA_S + kb + tig];
                af[mi][2] = Ab[r * LDA_S + kb + tig + 4];
                af[mi][3] = Ab[(r + 8) * LDA_S + kb + tig + 4];
            }
            uint32_t bf[4][2];
#pragma unroll
            for (int ni = 0; ni < 4; ni++) {
                int ccol = wn + ni * 8 + grp;
                uint32_t r0 = Bb[(kb + tig) * LDB_S + ccol];
                uint32_t r1 = Bb[(kb + tig + 4) * LDB_S + ccol];
                if (CVTB) {
                    bf[ni][0] = f2tf32(__uint_as_float(r0));
                    bf[ni][1] = f2tf32(__uint_as_float(r1));
                } else {
                    bf[ni][0] = r0;
                    bf[ni][1] = r1;
                }
            }
#pragma unroll
            for (int mi = 0; mi < 4; mi++)
#pragma unroll
                for (int ni = 0; ni < 4; ni++)
                    mma_tf32(acc[mi][ni], af[mi], bf[ni]);
        }
        __syncthreads();
    }

    const float* bias = biasBase ? (biasBase + (long long)e * biasStride) : nullptr;
#pragma unroll
    for (int mi = 0; mi < 4; mi++) {
        int rbase = wm + mi * 16 + grp;
#pragma unroll
        for (int half = 0; half < 2; half++) {
            int r = rbase + half * 8;
            int lrow = rowTile * BKM + r;
            if (lrow >= nrows) continue;
            int grow = s0 + lrow;
#pragma unroll
            for (int ni = 0; ni < 4; ni++) {
                int col = colStart + wn + ni * 8 + tig * 2;
                float v0 = acc[mi][ni][half * 2 + 0];
                float v1 = acc[mi][ni][half * 2 + 1];
                if (bias) { v0 += bias[col]; v1 += bias[col + 1]; }
                if (doGelu) {
                    v0 = rtf(gelu_tanh(v0));
                    v1 = rtf(gelu_tanh(v1));
                }
                if (residual) {
                    v0 += residual[(size_t)grow * ldc + col];
                    v1 += residual[(size_t)grow * ldc + col + 1];
                }
                if (col < N)     C[(size_t)grow * ldc + col] = v0;
                if (col + 1 < N) C[(size_t)grow * ldc + col + 1] = v1;
            }
        }
    }
}

// ---------------- fused idx scores | rope ----------------
__global__ __launch_bounds__(256) void idx_rope_kernel(
    const float* __restrict__ proj, float* __restrict__ out,
    float* __restrict__ qh, float* __restrict__ kh, float* __restrict__ vh)
{
    __shared__ float qshT[64][68];
    __shared__ float kshT[64][68];
    __shared__ float hsh[64][4];
    int tid = threadIdx.x;

    if (blockIdx.x < 1024) {
        int t0 = (blockIdx.x >> 5) * 64, s0 = (blockIdx.x & 31) * 64;
        const int tr = (tid >> 4) * 4, tc = (tid & 15) * 4;

        hsh[tid >> 2][tid & 3] = proj[(size_t)(t0 + (tid >> 2)) * NALL + OFF_HW + (tid & 3)];
        for (int i = tid; i < 4096; i += 256) {
            int r = i >> 6, c = i & 63;
            kshT[c][r] = proj[(size_t)(s0 + r) * NALL + OFF_KI + c];
        }
        float acc[4][4];
#pragma unroll
        for (int i = 0; i < 4; i++)
#pragma unroll
            for (int j = 0; j < 4; j++) acc[i][j] = 0.f;

        for (int h = 0; h < HIDX; h++) {
            __syncthreads();
            for (int i = tid; i < 4096; i += 256) {
                int r = i >> 6, c = i & 63;
                qshT[c][r] = proj[(size_t)(t0 + r) * NALL + OFF_QI + h * DIDX + c];
            }
            __syncthreads();
            float dot[4][4];
#pragma unroll
            for (int i = 0; i < 4; i++)
#pragma unroll
                for (int j = 0; j < 4; j++) dot[i][j] = 0.f;
            for (int kk = 0; kk < 64; kk++) {
                float4 a4 = *(const float4*)&qshT[kk][tr];
                float4 b4 = *(const float4*)&kshT[kk][tc];
                float a[4] = {a4.x, a4.y, a4.z, a4.w};
                float b[4] = {b4.x, b4.y, b4.z, b4.w};
#pragma unroll
                for (int i = 0; i < 4; i++)
#pragma unroll
                    for (int j = 0; j < 4; j++) dot[i][j] += a[i] * b[j];
            }
#pragma unroll
            for (int i = 0; i < 4; i++)
#pragma unroll
                for (int j = 0; j < 4; j++)
                    acc[i][j] += hsh[tr + i][h] * fmaxf(dot[i][j], 0.f);
        }
#pragma unroll
        for (int i = 0; i < 4; i++)
#pragma unroll
            for (int j = 0; j < 4; j++)
                out[(size_t)(t0 + tr + i) * TSEQ + (s0 + tc + j)] = acc[i][j] * 0.125f;
    } else {
        int idx = (blockIdx.x - 1024) * 256 + tid;
        int t = idx >> 10;
        int hd = idx & 1023;
        int h = hd >> 6, d = hd & 63;
        int j = d & 31;
        double invd = exp(-((double)(2 * j) / 64.0) * log(10000.0));
        float ang = (float)((double)t * invd);
        float c = cosf(ang), s = sinf(ang);
        const float* row = proj + (size_t)t * NALL;
        float q = row[OFF_Q + hd], k = row[OFF_K + hd], v = row[OFF_V + hd];
        float qr, kr;
        if (d < 32) {
            qr = q * c - row[OFF_Q + hd + 32] * s;
            kr = k * c - row[OFF_K + hd + 32] * s;
        } else {
            qr = q * c + row[OFF_Q + hd - 32] * s;
            kr = k * c + row[OFF_K + hd - 32] * s;
        }
        int o = ((h * TSEQ) + t) * HDIM + d;
        qh[o] = rtf(qr); kh[o] = rtf(kr); vh[o] = rtf(v);
    }
}

// ---------------- fused top-512 radix-select + mask (warp-scan; race-fixed) ----------------
__global__ __launch_bounds__(512) void topk_mask_kernel(
    const float* __restrict__ idxs, unsigned int* __restrict__ mask)
{
    __shared__ unsigned long long keys[2048];
    __shared__ unsigned int hist[256];
    __shared__ unsigned int wtot[8];
    __shared__ unsigned int sh_k;
    __shared__ unsigned long long sh_prefix;

    int t = blockIdx.x, tid = threadIdx.x;
    int lane = tid & 31;

    for (int i = tid; i < 2048; i += 512) {
        unsigned long long kk = 0ull;
        if (i <= t) {
            float v = idxs[(size_t)t * TSEQ + i];
            kk = ((unsigned long long)fmono(v) << 32) | (unsigned int)(2047 - i);
        }
        keys[i] = kk;
    }
    if (tid == 0) { sh_k = (unsigned int)KSEL; sh_prefix = 0ull; }
    __syncthreads();

    const int shifts[6] = {56, 48, 40, 32, 8, 0};
    unsigned long long prefix_mask = 0ull;
#pragma unroll
    for (int p = 0; p < 6; p++) {
        int shift = shifts[p];
        if (tid < 256) hist[tid] = 0u;
        __syncthreads();
        unsigned long long pref = sh_prefix;
        for (int i = tid; i < 2048; i += 512) {
            unsigned long long key = keys[i];
            if ((key & prefix_mask) == pref)
                atomicAdd(&hist[(unsigned int)(key >> shift) & 255u], 1u);
        }
        __syncthreads();
        // suffix sums: intra-warp shfl scan + 8 warp totals
        unsigned int s = 0u;
        if (tid < 256) {
            s = hist[tid];
#pragma unroll
            for (int off = 1; off < 32; off <<= 1) {
                unsigned int v = __shfl_down_sync(0xFFFFFFFFu, s, off);
                if (lane + off < 32) s += v;
            }
            if (lane == 0) wtot[tid >> 5] = s;
        }
        __syncthreads();
        if (tid < 256) {
            unsigned int add = 0u;
            for (int w2 = (tid >> 5) + 1; w2 < 8; w2++) add += wtot[w2];
            hist[tid] = s + add;
        }
        __syncthreads();
        unsigned int k = sh_k;
        __syncthreads();   // RACE FIX: all reads of sh_k complete before the matcher writes it
        if (tid < 256) {
            unsigned int s_here = hist[tid];
            unsigned int s_next = (tid == 255) ? 0u : hist[tid + 1];
            if (s_here >= k && s_next < k) {
                sh_prefix = pref | ((unsigned long long)tid << shift);
                sh_k = k - s_next;
            }
        }
        __syncthreads();
        prefix_mask |= (0xFFull << shift);
    }

    unsigned long long thr = sh_prefix;
    int w = tid >> 5;
    for (int word = w; word < 64; word += 16) {
        int i = word * 32 + lane;
        bool sel = (i <= t) && (keys[i] >= thr);
        unsigned int bal = __ballot_sync(0xFFFFFFFFu, sel);
        if (lane == 0) mask[t * 64 + word] = bal;
    }
}

// ---------------- dense masked flash attention (R11 version: register softmax, static smem) ----------------
__global__ void __launch_bounds__(256, 2) attn_flash(
    const float* __restrict__ qh, const float* __restrict__ kh, const float* __restrict__ vh,
    const unsigned int* __restrict__ mask, float* __restrict__ av)
{
    __shared__ float Ks[64][68];
    __shared__ float Vs[64][68];
    __shared__ float Ps[128][68];

    int qt = gridDim.x - 1 - blockIdx.x, h = blockIdx.y;
    int t0 = qt * 128;
    int tid = threadIdx.x;
    int warpId = tid >> 5, lane = tid & 31;
    int grp = lane >> 2, tig = lane & 3;
    int wm = warpId * 16;
    int r0 = wm + grp, r1 = wm + grp + 8;

    const float* Q0 = qh + ((size_t)h * TSEQ + t0) * HDIM;
    uint32_t qf[8][4];
#pragma unroll
    for (int ks = 0; ks < 8; ks++) {
        int kb = ks * 8;
        qf[ks][0] = __float_as_uint(Q0[r0 * HDIM + kb + tig]);
        qf[ks][1] = __float_as_uint(Q0[r1 * HDIM + kb + tig]);
        qf[ks][2] = __float_as_uint(Q0[r0 * HDIM + kb + tig + 4]);
        qf[ks][3] = __float_as_uint(Q0[r1 * HDIM + kb + tig + 4]);
    }

    float rowM0 = -INFINITY, rowM1 = -INFINITY;
    float rowL0 = 0.f, rowL1 = 0.f;

    float oacc[8][4];
#pragma unroll
    for (int ni = 0; ni < 8; ni++)
#pragma unroll
        for (int q = 0; q < 4; q++) oacc[ni][q] = 0.f;

    const float* Kb = kh + (size_t)h * TSEQ * HDIM;
    const float* Vb = vh + (size_t)h * TSEQ * HDIM;

    int ktMax = 2 * qt + 1;
    for (int kt = 0; kt <= ktMax; kt++) {
        __syncthreads();
        for (int i = tid; i < 1024; i += 256) {
            int row = i >> 4, c4 = (i & 15) * 4;
            *(float4*)&Ks[row][c4] = *(const float4*)(Kb + (size_t)(kt * 64 + row) * HDIM + c4);
            *(float4*)&Vs[row][c4] = *(const float4*)(Vb + (size_t)(kt * 64 + row) * HDIM + c4);
        }
        __syncthreads();

        float sacc[8][4];
#pragma unroll
        for (int ni = 0; ni < 8; ni++)
#pragma unroll
            for (int q = 0; q < 4; q++) sacc[ni][q] = 0.f;
#pragma unroll
        for (int ks = 0; ks < 8; ks++) {
            int kb = ks * 8;
#pragma unroll
            for (int ni = 0; ni < 8; ni++) {
                int n = ni * 8 + grp;
                uint32_t bf[2];
                bf[0] = __float_as_uint(Ks[n][kb + tig]);
                bf[1] = __float_as_uint(Ks[n][kb + tig + 4]);
                mma_tf32(sacc[ni], qf[ks], bf);
            }
        }

        unsigned int mw0[2], mw1[2];
        mw0[0] = mask[(t0 + r0) * 64 + kt * 2];
        mw0[1] = mask[(t0 + r0) * 64 + kt * 2 + 1];
        mw1[0] = mask[(t0 + r1) * 64 + kt * 2];
        mw1[1] = mask[(t0 + r1) * 64 + kt * 2 + 1];
#pragma unroll
        for (int ni = 0; ni < 8; ni++) {
            int c = ni * 8 + tig * 2;
            int wsel = c >> 5, b = c & 31;
            sacc[ni][0] = ((mw0[wsel] >> b) & 1u)       ? sacc[ni][0] * 0.125f : -INFINITY;
            sacc[ni][1] = ((mw0[wsel] >> (b + 1)) & 1u) ? sacc[ni][1] * 0.125f : -INFINITY;
            sacc[ni][2] = ((mw1[wsel] >> b) & 1u)       ? sacc[ni][2] * 0.125f : -INFINITY;
            sacc[ni][3] = ((mw1[wsel] >> (b + 1)) & 1u) ? sacc[ni][3] * 0.125f : -INFINITY;
        }

        float tmax0 = -INFINITY, tmax1 = -INFINITY;
#pragma unroll
        for (int ni = 0; ni < 8; ni++) {
            tmax0 = fmaxf(tmax0, fmaxf(sacc[ni][0], sacc[ni][1]));
            tmax1 = fmaxf(tmax1, fmaxf(sacc[ni][2], sacc[ni][3]));
        }
        tmax0 = fmaxf(tmax0, __shfl_xor_sync(0xFFFFFFFFu, tmax0, 1));
        tmax0 = fmaxf(tmax0, __shfl_xor_sync(0xFFFFFFFFu, tmax0, 2));
        tmax1 = fmaxf(tmax1, __shfl_xor_sync(0xFFFFFFFFu, tmax1, 1));
        tmax1 = fmaxf(tmax1, __shfl_xor_sync(0xFFFFFFFFu, tmax1, 2));

        float mnew0 = fmaxf(rowM0, tmax0), mnew1 = fmaxf(rowM1, tmax1);
        bool inval0 = (mnew0 == -INFINITY), inval1 = (mnew1 == -INFINITY);

        float tsum0 = 0.f, tsum1 = 0.f;
#pragma unroll
        for (int ni = 0; ni < 8; ni++) {
            int c = ni * 8 + tig * 2;
            float p00 = inval0 ? 0.f : expf(sacc[ni][0] - mnew0);
            float p01 = inval0 ? 0.f : expf(sacc[ni][1] - mnew0);
            float p10 = inval1 ? 0.f : expf(sacc[ni][2] - mnew1);
            float p11 = inval1 ? 0.f : expf(sacc[ni][3] - mnew1);
            Ps[r0][c]     = rtf(p00);
            Ps[r0][c + 1] = rtf(p01);
            Ps[r1][c]     = rtf(p10);
            Ps[r1][c + 1] = rtf(p11);
            tsum0 += p00; tsum0 += p01;
            tsum1 += p10; tsum1 += p11;
        }
        tsum0 += __shfl_xor_sync(0xFFFFFFFFu, tsum0, 1);
        tsum0 += __shfl_xor_sync(0xFFFFFFFFu, tsum0, 2);
        tsum1 += __shfl_xor_sync(0xFFFFFFFFu, tsum1, 1);
        tsum1 += __shfl_xor_sync(0xFFFFFFFFu, tsum1, 2);

        float sc0 = inval0 ? 1.f : expf(rowM0 - mnew0);
        float sc1 = inval1 ? 1.f : expf(rowM1 - mnew1);
        rowM0 = mnew0; rowM1 = mnew1;
        rowL0 = rowL0 * sc0 + tsum0;
        rowL1 = rowL1 * sc1 + tsum1;

#pragma unroll
        for (int ni = 0; ni < 8; ni++) {
            oacc[ni][0] *= sc0; oacc[ni][1] *= sc0;
            oacc[ni][2] *= sc1; oacc[ni][3] *= sc1;
        }
        __syncwarp();

#pragma unroll
        for (int ks = 0; ks < 8; ks++) {
            int kb = ks * 8;
            uint32_t pa[4];
            pa[0] = __float_as_uint(Ps[r0][kb + tig]);
            pa[1] = __float_as_uint(Ps[r1][kb + tig]);
            pa[2] = __float_as_uint(Ps[r0][kb + tig + 4]);
            pa[3] = __float_as_uint(Ps[r1][kb + tig + 4]);
#pragma unroll
            for (int ni = 0; ni < 8; ni++) {
                int n = ni * 8 + grp;
                uint32_t vf[2];
                vf[0] = __float_as_uint(Vs[kb + tig][n]);
                vf[1] = __float_as_uint(Vs[kb + tig + 4][n]);
                mma_tf32(oacc[ni], pa, vf);
            }
        }
    }

    float i0 = 1.f / rowL0;
    float i1 = 1.f / rowL1;
#pragma unroll
    for (int ni = 0; ni < 8; ni++) {
        int c = ni * 8 + tig * 2;
        size_t o0 = (size_t)(t0 + r0) * DMODEL + h * HDIM + c;
        size_t o1 = (size_t)(t0 + r1) * DMODEL + h * HDIM + c;
        av[o0]     = rtf(oacc[ni][0] * i0);
        av[o0 + 1] = rtf(oacc[ni][1] * i0);
        av[o1]     = rtf(oacc[ni][2] * i1);
        av[o1 + 1] = rtf(oacc[ni][3] * i1);
    }
}

// ---------------- fused rmsnorm2 + router (bit-identical to split version) ----------------
__global__ __launch_bounds__(256) void norm2_router_kernel(
    const float* __restrict__ x1, const float* __restrict__ norm2_w,
    const float* __restrict__ rw, const float* __restrict__ rb,
    float* __restrict__ x2n, float* __restrict__ probs,
    int* __restrict__ topE, float* __restrict__ topG)
{
    int t = blockIdx.x, tid = threadIdx.x;
    __shared__ float red[256];
    __shared__ float lg[8];
    const float* xr = x1 + (size_t)t * DMODEL;

    float s = 0.f;
    for (int d = tid; d < DMODEL; d += 256) { float v = xr[d]; s += v * v; }
    red[tid] = s; __syncthreads();
    for (int o = 128; o > 0; o >>= 1) { if (tid < o) red[tid] += red[tid + o]; __syncthreads(); }
    float rms = rsqrtf(red[0] / (float)DMODEL + 1e-6f);
    __syncthreads();

    float vloc[4];
    float* yr = x2n + (size_t)t * DMODEL;
    {
        int k = 0;
        for (int d = tid; d < DMODEL; d += 256, k++) {
            float v = xr[d] * rms * norm2_w[d];
            vloc[k] = v;
            yr[d] = rtf(v);
        }
    }

    float acc[8];
#pragma unroll
    for (int e = 0; e < 8; e++) acc[e] = 0.f;
    {
        int k = 0;
        for (int d = tid; d < DMODEL; d += 256, k++) {
            float xv = vloc[k];
#pragma unroll
            for (int e = 0; e < 8; e++) acc[e] += xv * rw[(size_t)d * NEXP + e];
        }
    }
    for (int e = 0; e < 8; e++) {
        red[tid] = acc[e]; __syncthreads();
        for (int o = 128; o > 0; o >>= 1) { if (tid < o) red[tid] += red[tid + o]; __syncthreads(); }
        if (tid == 0) lg[e] = red[0] + rb[e];
        __syncthreads();
    }
    if (tid == 0) {
        float m = lg[0];
        for (int e = 1; e < 8; e++) m = fmaxf(m, lg[e]);
        float p[8], sum = 0.f;
        for (int e = 0; e < 8; e++) { p[e] = expf(lg[e] - m); sum += p[e]; }
        for (int e = 0; e < 8; e++) p[e] /= sum;
        int e0 = 0;
        for (int e = 1; e < 8; e++) if (p[e] > p[e0]) e0 = e;
        int e1 = -1;
        for (int e = 0; e < 8; e++) if (e != e0 && (e1 < 0 || p[e] > p[e1])) e1 = e;
        float denom = p[e0] + p[e1];
        for (int e = 0; e < 8; e++) probs[(size_t)t * NEXP + e] = p[e];
        topE[t * 2 + 0] = e0; topE[t * 2 + 1] = e1;
        topG[t * 2 + 0] = p[e0] / denom; topG[t * 2 + 1] = p[e1] / denom;
    }
}

// ---------------- deterministic grouping (warp-ballot scan) ----------------
__global__ __launch_bounds__(256) void group_kernel(
    const int* __restrict__ topE, int* __restrict__ counts,
    int* __restrict__ segoff, int* __restrict__ rowmap,
    int* __restrict__ slotpos)
{
    __shared__ short sE[TSEQ * 2];
    __shared__ int sSeg[NEXP + 1];
    __shared__ int sCnt[NEXP];
    int tid = threadIdx.x;
    int lane = tid & 31, w = tid >> 5;
    for (int i = tid; i < TSEQ * 2; i += 256) sE[i] = (short)topE[i];
    __syncthreads();

    {
        int e = w;
        int c = 0;
        for (int i0 = 0; i0 < TSEQ * 2; i0 += 32) {
            unsigned int m = __ballot_sync(0xFFFFFFFFu, sE[i0 + lane] == e);
            c += __popc(m);
        }
        if (lane == 0) { counts[e] = c; sCnt[e] = c; }
    }
    __syncthreads();
    if (tid == 0) {
        int o = 0;
        for (int i = 0; i < 8; i++) { sSeg[i] = o; segoff[i] = o; o += sCnt[i]; }
        sSeg[8] = o; segoff[8] = o;
    }
    __syncthreads();

    {
        int e = w;
        int pos = sSeg[e];
        unsigned int ltmask = (1u << lane) - 1u;
        for (int i0 = 0; i0 < TSEQ * 2; i0 += 32) {
            int i = i0 + lane;
            bool match = (sE[i] == e);
            unsigned int m = __ballot_sync(0xFFFFFFFFu, match);
            if (match) {
                int off = __popc(m & ltmask);
                rowmap[pos + off] = i >> 1;
                slotpos[i] = pos + off;
            }
            pos += __popc(m);
        }
    }
}

// ---------------- fused combine | aux ----------------
__global__ __launch_bounds__(256) void combine_aux_kernel(
    const float* __restrict__ x1, const float* __restrict__ y,
    const int* __restrict__ slotpos, const float* __restrict__ topG,
    const float* __restrict__ probs, const int* __restrict__ counts,
    float* __restrict__ out, float* __restrict__ outAux)
{
    int tid = threadIdx.x;
    if (blockIdx.x < (TSEQ * DMODEL / 4) / 256) {
        int i4 = blockIdx.x * 256 + tid;
        int t = i4 >> 8, d4 = (i4 & 255) * 4;
        int p0 = slotpos[t * 2 + 0], p1 = slotpos[t * 2 + 1];
        float g0 = topG[t * 2 + 0], g1 = topG[t * 2 + 1];
        float4 a = *(const float4*)(x1 + (size_t)t * DMODEL + d4);
        float4 y0 = *(const float4*)(y + (size_t)p0 * DMODEL + d4);
        float4 y1 = *(const float4*)(y + (size_t)p1 * DMODEL + d4);
        float4 r;
        r.x = a.x + g0 * y0.x + g1 * y1.x;
        r.y = a.y + g0 * y0.y + g1 * y1.y;
        r.z = a.z + g0 * y0.z + g1 * y1.z;
        r.w = a.w + g0 * y0.w + g1 * y1.w;
        *(float4*)(out + (size_t)t * DMODEL + d4) = r;
    } else {
        __shared__ float red[256];
        float a = 0.f;
        for (int e = 0; e < 8; e++) {
            float s = 0.f;
            for (int t = tid; t < TSEQ; t += 256) s += probs[(size_t)t * NEXP + e];
            red[tid] = s; __syncthreads();
            for (int o = 128; o > 0; o >>= 1) { if (tid < o) red[tid] += red[tid + o]; __syncthreads(); }
            if (tid == 0) a += (float)counts[e] * red[0];
            __syncthreads();
        }
        if (tid == 0) *outAux = 8.f * a / ((float)TSEQ * (float)TSEQ);
    }
}

// ---------------- host launch ----------------
#define GETSYM(ptr, sym) do { void* _p_; cudaGetSymbolAddress(&_p_, sym); ptr = (decltype(ptr))_p_; } while (0)

extern "C" void kernel_launch(void* const* d_in, const int* in_sizes, int n_in,
                              void* d_out, int out_size)
{
    const float* x        = (const float*)d_in[0];
    const float* norm1_w  = (const float*)d_in[1];
    const float* norm2_w  = (const float*)d_in[2];
    const float* wq_idx   = (const float*)d_in[3];
    const float* wk_idx   = (const float*)d_in[4];
    const float* w_head   = (const float*)d_in[5];
    const float* wq       = (const float*)d_in[6];
    const float* wk       = (const float*)d_in[7];
    const float* wv       = (const float*)d_in[8];
    const float* wo       = (const float*)d_in[9];
    const float* router_w = (const float*)d_in[10];
    const float* router_b = (const float*)d_in[11];
    const float* w1       = (const float*)d_in[12];
    const float* b1       = (const float*)d_in[13];
    const float* w2       = (const float*)d_in[14];
    const float* b2       = (const float*)d_in[15];

    float* out    = (float*)d_out;
    float* auxp   = out + (size_t)TSEQ * DMODEL;
    float* idxout = auxp + 1;

    float *p_xn, *p_all, *p_qh, *p_kh, *p_vh;
    float *p_av, *p_x1, *p_x2n, *p_probs, *p_topG, *p_mid, *p_y;
    float *p_woc, *p_wall;
    int *p_topE, *p_counts, *p_segoff, *p_rowmap, *p_slotpos;
    unsigned int *p_mask;
    GETSYM(p_xn, g_xn); GETSYM(p_all, g_all);
    GETSYM(p_qh, g_qh); GETSYM(p_kh, g_kh); GETSYM(p_vh, g_vh);
    GETSYM(p_av, g_av); GETSYM(p_x1, g_x1); GETSYM(p_x2n, g_x2n);
    GETSYM(p_probs, g_probs); GETSYM(p_topE, g_topE); GETSYM(p_topG, g_topG);
    GETSYM(p_counts, g_counts); GETSYM(p_segoff, g_segoff);
    GETSYM(p_rowmap, g_rowmap); GETSYM(p_slotpos, g_slotpos);
    GETSYM(p_mid, g_mid); GETSYM(p_y, g_yy); GETSYM(p_mask, g_mask);
    GETSYM(p_woc, g_woc); GETSYM(p_wall, g_wall);

    cudaFuncSetAttribute(tgemm<0>, cudaFuncAttributeMaxDynamicSharedMemorySize, TG_SMEM_BYTES);
    cudaFuncSetAttribute(tgemm<1>, cudaFuncAttributeMaxDynamicSharedMemorySize, TG_SMEM_BYTES);

    // 1. fused prep: rmsnorm1 | pack_all | round4(wo)
    prep_kernel<<<TSEQ + PACK_BLOCKS + WO4_BLOCKS, 256>>>(
        x, norm1_w, p_xn, wq, wk, wv, wq_idx, wk_idx, w_head, p_wall, wo, p_woc);

    // 2. single fused projection GEMM (qkv + indexer, N=3396)
    tgemm<0><<<dim3((NALL + 127) / 128, 16, 1), 256, TG_SMEM_BYTES>>>(
        p_xn, DMODEL, nullptr, p_wall, 0, nullptr, 0,
        nullptr, p_all, NALL, nullptr, TSEQ, NALL, DMODEL, 0);

    // 3. fused indexer scores | rope, then top-512 mask
    idx_rope_kernel<<<1024 + (TSEQ * DMODEL) / 256, 256>>>(p_all, idxout, p_qh, p_kh, p_vh);
    topk_mask_kernel<<<TSEQ, 512>>>(idxout, p_mask);

    // 4. dense masked flash attention (R11 version)
    attn_flash<<<dim3(TSEQ / 128, NHEAD), 256>>>(p_qh, p_kh, p_vh, p_mask, p_av);

    // 5. output projection + residual
    tgemm<0><<<dim3(8, 16, 1), 256, TG_SMEM_BYTES>>>(p_av, DMODEL, nullptr, p_woc, 0, nullptr, 0,
        x, p_x1, DMODEL, nullptr, TSEQ, DMODEL, DMODEL, 0);

    // 6. fused norm2+router, grouping
    norm2_router_kernel<<<TSEQ, 256>>>(p_x1, norm2_w, router_w, router_b,
                                       p_x2n, p_probs, p_topE, p_topG);
    group_kernel<<<1, 256>>>(p_topE, p_counts, p_segoff, p_rowmap, p_slotpos);

    // 7. MoE grouped GEMMs (raw weights, tf32 cvt at fragment load)
    tgemm<1><<<dim3(DFFN / 128, 16, NEXP), 256, TG_SMEM_BYTES>>>(
        p_x2n, DMODEL, p_rowmap, w1, (long long)DMODEL * DFFN, b1, DFFN,
        nullptr, p_mid, DFFN, p_segoff, 0, DFFN, DMODEL, 1);
    tgemm<1><<<dim3(DMODEL / 128, 16, NEXP), 256, TG_SMEM_BYTES>>>(
        p_mid, DFFN, nullptr, w2, (long long)DFFN * DMODEL, b2, DMODEL,
        nullptr, p_y, DMODEL, p_segoff, 0, DMODEL, DFFN, 0);

    // 8. fused combine | aux
    combine_aux_kernel<<<(TSEQ * DMODEL / 4) / 256 + 1, 256>>>(
        p_x1, p_y, p_slotpos, p_topG, p_probs, p_counts, out, auxp);
}

// round 14
// speedup vs baseline: 1.2648x; 1.0379x over previous
#include <cuda_runtime.h>
#include <math.h>
#include <stdint.h>

// ---------------- constants ----------------
static const int TSEQ = 2048;
static const int DMODEL = 1024;
static const int NHEAD = 16;
static const int HDIM = 64;
static const int DFFN = 4096;
static const int NEXP = 8;
static const int HIDX = 4;
static const int DIDX = 64;
static const int KSEL = 512;
static const int NALL = 3 * DMODEL + HIDX * DIDX + DIDX + HIDX;  // 3396
static const int OFF_Q = 0;
static const int OFF_K = DMODEL;
static const int OFF_V = 2 * DMODEL;
static const int OFF_QI = 3 * DMODEL;           // 3072
static const int OFF_KI = OFF_QI + HIDX * DIDX; // 3328
static const int OFF_HW = OFF_KI + DIDX;        // 3392
static const int PACK_BLOCKS = (DMODEL * NALL) / 256;      // 13584
static const int WO4_BLOCKS = (DMODEL * DMODEL / 4) / 256; // 1024

// ---------------- device scratch ----------------
__device__ float g_xn[TSEQ * DMODEL];
__device__ float g_all[TSEQ * NALL];
__device__ float g_qh[TSEQ * DMODEL];
__device__ float g_kh[TSEQ * DMODEL];
__device__ float g_vh[TSEQ * DMODEL];
__device__ float g_av[TSEQ * DMODEL];
__device__ float g_x1[TSEQ * DMODEL];
__device__ float g_x2n[TSEQ * DMODEL];   // tf32-rounded (MoE GEMM operand)
__device__ float g_probs[TSEQ * NEXP];
__device__ int   g_topE[TSEQ * 2];
__device__ float g_topG[TSEQ * 2];
__device__ int   g_counts[NEXP];
__device__ int   g_segoff[NEXP + 1];
__device__ int   g_rowmap[TSEQ * 2];
__device__ int   g_slotpos[TSEQ * 2];
__device__ float g_mid[(size_t)(TSEQ * 2) * DFFN];
__device__ float g_yy[(size_t)(TSEQ * 2) * DMODEL];
__device__ unsigned int g_mask[TSEQ * (TSEQ / 32)];
__device__ float g_woc[DMODEL * DMODEL];
__device__ float g_wall[DMODEL * NALL];

// ---------------- helpers ----------------
__device__ __forceinline__ float gelu_tanh(float x) {
    float x3 = x * x * x;
    float u = 0.7978845608028654f * (x + 0.044715f * x3);
    return 0.5f * x * (1.0f + tanhf(u));
}

__device__ __forceinline__ unsigned int fmono(float f) {
    unsigned int u = __float_as_uint(f);
    return (u & 0x80000000u) ? ~u : (u | 0x80000000u);
}

__device__ __forceinline__ uint32_t f2tf32(float f) {
    uint32_t r;
    asm("cvt.rna.tf32.f32 %0, %1;" : "=r"(r) : "f"(f));
    return r;
}
__device__ __forceinline__ float rtf(float f) { return __uint_as_float(f2tf32(f)); }

__device__ __forceinline__ void cp16(uint32_t dst, const float* src, int sz) {
    asm volatile("cp.async.cg.shared.global [%0], [%1], 16, %2;" :: "r"(dst), "l"(src), "r"(sz));
}

__device__ __forceinline__ void mma_tf32(float* c, const uint32_t* a, const uint32_t* b) {
    asm volatile(
        "mma.sync.aligned.m16n8k8.row.col.f32.tf32.tf32.f32 "
        "{%0,%1,%2,%3}, {%4,%5,%6,%7}, {%8,%9}, {%0,%1,%2,%3};"
        : "+f"(c[0]), "+f"(c[1]), "+f"(c[2]), "+f"(c[3])
        : "r"(a[0]), "r"(a[1]), "r"(a[2]), "r"(a[3]), "r"(b[0]), "r"(b[1]));
}

// ---------------- fused prep: rmsnorm1 | pack_all | round4(wo) ----------------
__global__ __launch_bounds__(256) void prep_kernel(
    const float* __restrict__ x, const float* __restrict__ norm1_w, float* __restrict__ xn,
    const float* __restrict__ wq, const float* __restrict__ wk, const float* __restrict__ wv,
    const float* __restrict__ wq_idx, const float* __restrict__ wk_idx,
    const float* __restrict__ w_head, float* __restrict__ wall,
    const float* __restrict__ wo, float* __restrict__ woc)
{
    int b = blockIdx.x, tid = threadIdx.x;
    if (b < TSEQ) {
        __shared__ float red[256];
        const float* xr = x + (size_t)b * DMODEL;
        float s = 0.f;
        for (int d = tid; d < DMODEL; d += 256) { float v = xr[d]; s += v * v; }
        red[tid] = s; __syncthreads();
        for (int o = 128; o > 0; o >>= 1) { if (tid < o) red[tid] += red[tid + o]; __syncthreads(); }
        float rms = rsqrtf(red[0] / (float)DMODEL + 1e-6f);
        float* yr = xn + (size_t)b * DMODEL;
        for (int d = tid; d < DMODEL; d += 256) yr[d] = rtf(xr[d] * rms * norm1_w[d]);
    } else if (b < TSEQ + PACK_BLOCKS) {
        int i = (b - TSEQ) * 256 + tid;
        int d = i / NALL, j = i - d * NALL;
        float v;
        if (j < OFF_K)        v = wq[d * DMODEL + j];
        else if (j < OFF_V)   v = wk[d * DMODEL + (j - OFF_K)];
        else if (j < OFF_QI)  v = wv[d * DMODEL + (j - OFF_V)];
        else if (j < OFF_KI)  v = wq_idx[d * (HIDX * DIDX) + (j - OFF_QI)];
        else if (j < OFF_HW)  v = wk_idx[d * DIDX + (j - OFF_KI)];
        else                  v = w_head[d * HIDX + (j - OFF_HW)];
        wall[i] = rtf(v);
    } else {
        int i = (b - TSEQ - PACK_BLOCKS) * 256 + tid;
        float4 v = ((const float4*)wo)[i];
        v.x = rtf(v.x); v.y = rtf(v.y); v.z = rtf(v.z); v.w = rtf(v.w);
        ((float4*)woc)[i] = v;
    }
}

// ---------------- unified tf32 tensor GEMM (TBM=128, 3-stage, 2 CTA/SM) ----------------
// LDB_S=136 (mod 32 == 8) makes B fragment loads bank-conflict-free.
#define BKM 128
#define BKK 32
#define LDA_S 36
#define LDB_S 136
#define A_STAGE (BKM * LDA_S)
#define B_STAGE (BKK * LDB_S)
#define STAGE_FLOATS (A_STAGE + B_STAGE)
#define NSTAGE 3
#define TG_SMEM_BYTES (NSTAGE * STAGE_FLOATS * 4)

extern __shared__ float smem_dyn[];

template <int CVTB>
__global__ void __launch_bounds__(256, 2) tgemm(
    const float* __restrict__ A, int lda,
    const int* __restrict__ rowmap,
    const float* __restrict__ Bbase, long long strideB,
    const float* __restrict__ biasBase, int biasStride,
    const float* __restrict__ residual,
    float* __restrict__ C, int ldc,
    const int* __restrict__ segoff,
    int M, int N, int K, int doGelu)
{
    int e = blockIdx.z;
    int s0 = 0, nrows = M;
    if (segoff) { s0 = segoff[e]; nrows = segoff[e + 1] - s0; }
    int rowTile = blockIdx.y;
    if (rowTile * BKM >= nrows) return;
    int colStart = blockIdx.x * 128;
    const float* B = Bbase + (long long)e * strideB;

    int tid = threadIdx.x;
    int warpId = tid >> 5, lane = tid & 31;
    int grp = lane >> 2, tig = lane & 3;
    int wm = (warpId >> 2) * 64;
    int wn = (warpId & 3) * 32;

    uint32_t sbase = (uint32_t)__cvta_generic_to_shared(smem_dyn);

    const float* aSrc[4]; int aSz[4]; uint32_t aDst[4];
    const float* bSrc[4]; int bSz[4]; uint32_t bDst[4];
#pragma unroll
    for (int i = 0; i < 4; i++) {
        int c = tid + i * 256;
        int arow = c >> 3, akc = (c & 7) * 4;
        int lrow = rowTile * BKM + arow;
        bool v = lrow < nrows;
        int gidx = 0;
        if (v) {
            int base = s0 + lrow;
            gidx = rowmap ? rowmap[base] : base;
        }
        aSrc[i] = A + (size_t)gidx * lda + akc;
        aSz[i] = v ? 16 : 0;
        aDst[i] = (uint32_t)((arow * LDA_S + akc) * 4);

        int brow = c >> 5, bnc = (c & 31) * 4;
        int col = colStart + bnc;
        bool bv = (col + 4 <= N);
        bSz[i] = bv ? 16 : 0;
        bSrc[i] = B + (size_t)brow * N + (bv ? col : 0);
        bDst[i] = (uint32_t)((A_STAGE + brow * LDB_S + bnc) * 4);
    }

    float acc[4][4][4];
#pragma unroll
    for (int mi = 0; mi < 4; mi++)
#pragma unroll
        for (int ni = 0; ni < 4; ni++)
#pragma unroll
            for (int q = 0; q < 4; q++) acc[mi][ni][q] = 0.f;

    int KT = K / BKK;

#pragma unroll
    for (int p = 0; p < NSTAGE - 1; p++) {
        if (p < KT) {
            int k0 = p * BKK;
            uint32_t sb = sbase + (uint32_t)((p % NSTAGE) * STAGE_FLOATS * 4);
#pragma unroll
            for (int i = 0; i < 4; i++) cp16(sb + aDst[i], aSrc[i] + k0, aSz[i]);
#pragma unroll
            for (int i = 0; i < 4; i++) cp16(sb + bDst[i], bSrc[i] + (size_t)k0 * N, bSz[i]);
            asm volatile("cp.async.commit_group;");
        }
    }

    for (int it = 0; it < KT; it++) {
        if (it + NSTAGE - 1 < KT) {
            int k0 = (it + NSTAGE - 1) * BKK;
            uint32_t sb = sbase + (uint32_t)(((it + NSTAGE - 1) % NSTAGE) * STAGE_FLOATS * 4);
#pragma unroll
            for (int i = 0; i < 4; i++) cp16(sb + aDst[i], aSrc[i] + k0, aSz[i]);
#pragma unroll
            for (int i = 0; i < 4; i++) cp16(sb + bDst[i], bSrc[i] + (size_t)k0 * N, bSz[i]);
            asm volatile("cp.async.commit_group;");
        }
        int pend = KT - 1 - it;
        if (pend > NSTAGE - 1) pend = NSTAGE - 1;
        if (pend >= 2)      asm volatile("cp.async.wait_group 2;");
        else if (pend == 1) asm volatile("cp.async.wait_group 1;");
        else                asm volatile("cp.async.wait_group 0;");
        __syncthreads();

        const uint32_t* Ab = (const uint32_t*)(smem_dyn + (size_t)(it % NSTAGE) * STAGE_FLOATS);
        const uint32_t* Bb = Ab + A_STAGE;
#pragma unroll
        for (int ks = 0; ks < 4; ks++) {
            int kb = ks * 8;
            uint32_t af[4][4];
#pragma unroll
            for (int mi = 0; mi < 4; mi++) {
                int r = wm + mi * 16 + grp;
                af[mi][0] = Ab[r * LDA_S + kb + tig];
                af[mi][1] = Ab[(r + 8) * LDA_S + kb + tig];
                af[mi][2] = Ab[r * LDA_S + kb + tig + 4];
                af[mi][3] = Ab[(r + 8) * LDA_S + kb + tig + 4];
            }
            uint32_t bf[4][2];
#pragma unroll
            for (int ni = 0; ni < 4; ni++) {
                int ccol = wn + ni * 8 + grp;
                uint32_t r0 = Bb[(kb + tig) * LDB_S + ccol];
                uint32_t r1 = Bb[(kb + tig + 4) * LDB_S + ccol];
                if (CVTB) {
                    bf[ni][0] = f2tf32(__uint_as_float(r0));
                    bf[ni][1] = f2tf32(__uint_as_float(r1));
                } else {
                    bf[ni][0] = r0;
                    bf[ni][1] = r1;
                }
            }
#pragma unroll
            for (int mi = 0; mi < 4; mi++)
#pragma unroll
                for (int ni = 0; ni < 4; ni++)
                    mma_tf32(acc[mi][ni], af[mi], bf[ni]);
        }
        __syncthreads();
    }

    const float* bias = biasBase ? (biasBase + (long long)e * biasStride) : nullptr;
#pragma unroll
    for (int mi = 0; mi < 4; mi++) {
        int rbase = wm + mi * 16 + grp;
#pragma unroll
        for (int half = 0; half < 2; half++) {
            int r = rbase + half * 8;
            int lrow = rowTile * BKM + r;
            if (lrow >= nrows) continue;
            int grow = s0 + lrow;
#pragma unroll
            for (int ni = 0; ni < 4; ni++) {
                int col = colStart + wn + ni * 8 + tig * 2;
                float v0 = acc[mi][ni][half * 2 + 0];
                float v1 = acc[mi][ni][half * 2 + 1];
                if (bias) { v0 += bias[col]; v1 += bias[col + 1]; }
                if (doGelu) {
                    v0 = rtf(gelu_tanh(v0));
                    v1 = rtf(gelu_tanh(v1));
                }
                if (residual) {
                    v0 += residual[(size_t)grow * ldc + col];
                    v1 += residual[(size_t)grow * ldc + col + 1];
                }
                if (col < N)     C[(size_t)grow * ldc + col] = v0;
                if (col + 1 < N) C[(size_t)grow * ldc + col + 1] = v1;
            }
        }
    }
}

// ---------------- fused idx scores | rope ----------------
__global__ __launch_bounds__(256) void idx_rope_kernel(
    const float* __restrict__ proj, float* __restrict__ out,
    float* __restrict__ qh, float* __restrict__ kh, float* __restrict__ vh)
{
    __shared__ float qshT[64][68];
    __shared__ float kshT[64][68];
    __shared__ float hsh[64][4];
    int tid = threadIdx.x;

    if (blockIdx.x < 1024) {
        int t0 = (blockIdx.x >> 5) * 64, s0 = (blockIdx.x & 31) * 64;
        const int tr = (tid >> 4) * 4, tc = (tid & 15) * 4;

        hsh[tid >> 2][tid & 3] = proj[(size_t)(t0 + (tid >> 2)) * NALL + OFF_HW + (tid & 3)];
        for (int i = tid; i < 4096; i += 256) {
            int r = i >> 6, c = i & 63;
            kshT[c][r] = proj[(size_t)(s0 + r) * NALL + OFF_KI + c];
        }
        float acc[4][4];
#pragma unroll
        for (int i = 0; i < 4; i++)
#pragma unroll
            for (int j = 0; j < 4; j++) acc[i][j] = 0.f;

        for (int h = 0; h < HIDX; h++) {
            __syncthreads();
            for (int i = tid; i < 4096; i += 256) {
                int r = i >> 6, c = i & 63;
                qshT[c][r] = proj[(size_t)(t0 + r) * NALL + OFF_QI + h * DIDX + c];
            }
            __syncthreads();
            float dot[4][4];
#pragma unroll
            for (int i = 0; i < 4; i++)
#pragma unroll
                for (int j = 0; j < 4; j++) dot[i][j] = 0.f;
            for (int kk = 0; kk < 64; kk++) {
                float4 a4 = *(const float4*)&qshT[kk][tr];
                float4 b4 = *(const float4*)&kshT[kk][tc];
                float a[4] = {a4.x, a4.y, a4.z, a4.w};
                float b[4] = {b4.x, b4.y, b4.z, b4.w};
#pragma unroll
                for (int i = 0; i < 4; i++)
#pragma unroll
                    for (int j = 0; j < 4; j++) dot[i][j] += a[i] * b[j];
            }
#pragma unroll
            for (int i = 0; i < 4; i++)
#pragma unroll
                for (int j = 0; j < 4; j++)
                    acc[i][j] += hsh[tr + i][h] * fmaxf(dot[i][j], 0.f);
        }
#pragma unroll
        for (int i = 0; i < 4; i++)
#pragma unroll
            for (int j = 0; j < 4; j++)
                out[(size_t)(t0 + tr + i) * TSEQ + (s0 + tc + j)] = acc[i][j] * 0.125f;
    } else {
        int idx = (blockIdx.x - 1024) * 256 + tid;
        int t = idx >> 10;
        int hd = idx & 1023;
        int h = hd >> 6, d = hd & 63;
        int j = d & 31;
        double invd = exp(-((double)(2 * j) / 64.0) * log(10000.0));
        float ang = (float)((double)t * invd);
        float c = cosf(ang), s = sinf(ang);
        const float* row = proj + (size_t)t * NALL;
        float q = row[OFF_Q + hd], k = row[OFF_K + hd], v = row[OFF_V + hd];
        float qr, kr;
        if (d < 32) {
            qr = q * c - row[OFF_Q + hd + 32] * s;
            kr = k * c - row[OFF_K + hd + 32] * s;
        } else {
            qr = q * c + row[OFF_Q + hd - 32] * s;
            kr = k * c + row[OFF_K + hd - 32] * s;
        }
        int o = ((h * TSEQ) + t) * HDIM + d;
        qh[o] = rtf(qr); kh[o] = rtf(kr); vh[o] = rtf(v);
    }
}

// ---------------- fused top-512 radix-select + mask (warp-scan; race-fixed) ----------------
__global__ __launch_bounds__(512) void topk_mask_kernel(
    const float* __restrict__ idxs, unsigned int* __restrict__ mask)
{
    __shared__ unsigned long long keys[2048];
    __shared__ unsigned int hist[256];
    __shared__ unsigned int wtot[8];
    __shared__ unsigned int sh_k;
    __shared__ unsigned long long sh_prefix;

    int t = blockIdx.x, tid = threadIdx.x;
    int lane = tid & 31;

    for (int i = tid; i < 2048; i += 512) {
        unsigned long long kk = 0ull;
        if (i <= t) {
            float v = idxs[(size_t)t * TSEQ + i];
            kk = ((unsigned long long)fmono(v) << 32) | (unsigned int)(2047 - i);
        }
        keys[i] = kk;
    }
    if (tid == 0) { sh_k = (unsigned int)KSEL; sh_prefix = 0ull; }
    __syncthreads();

    const int shifts[6] = {56, 48, 40, 32, 8, 0};
    unsigned long long prefix_mask = 0ull;
#pragma unroll
    for (int p = 0; p < 6; p++) {
        int shift = shifts[p];
        if (tid < 256) hist[tid] = 0u;
        __syncthreads();
        unsigned long long pref = sh_prefix;
        for (int i = tid; i < 2048; i += 512) {
            unsigned long long key = keys[i];
            if ((key & prefix_mask) == pref)
                atomicAdd(&hist[(unsigned int)(key >> shift) & 255u], 1u);
        }
        __syncthreads();
        unsigned int s = 0u;
        if (tid < 256) {
            s = hist[tid];
#pragma unroll
            for (int off = 1; off < 32; off <<= 1) {
                unsigned int v = __shfl_down_sync(0xFFFFFFFFu, s, off);
                if (lane + off < 32) s += v;
            }
            if (lane == 0) wtot[tid >> 5] = s;
        }
        __syncthreads();
        if (tid < 256) {
            unsigned int add = 0u;
            for (int w2 = (tid >> 5) + 1; w2 < 8; w2++) add += wtot[w2];
            hist[tid] = s + add;
        }
        __syncthreads();
        unsigned int k = sh_k;
        __syncthreads();   // all reads of sh_k complete before the matcher writes it
        if (tid < 256) {
            unsigned int s_here = hist[tid];
            unsigned int s_next = (tid == 255) ? 0u : hist[tid + 1];
            if (s_here >= k && s_next < k) {
                sh_prefix = pref | ((unsigned long long)tid << shift);
                sh_k = k - s_next;
            }
        }
        __syncthreads();
        prefix_mask |= (0xFFull << shift);
    }

    unsigned long long thr = sh_prefix;
    int w = tid >> 5;
    for (int word = w; word < 64; word += 16) {
        int i = word * 32 + lane;
        bool sel = (i <= t) && (keys[i] >= thr);
        unsigned int bal = __ballot_sync(0xFFFFFFFFu, sel);
        if (lane == 0) mask[t * 64 + word] = bal;
    }
}

// ---------------- dense masked flash attention (register softmax; Vs padded to 72) ----------------
__global__ void __launch_bounds__(256, 2) attn_flash(
    const float* __restrict__ qh, const float* __restrict__ kh, const float* __restrict__ vh,
    const unsigned int* __restrict__ mask, float* __restrict__ av)
{
    __shared__ float Ks[64][68];
    __shared__ float Vs[64][72];   // 72 mod 32 == 8 -> conflict-free V fragment loads
    __shared__ float Ps[128][68];

    int qt = gridDim.x - 1 - blockIdx.x, h = blockIdx.y;
    int t0 = qt * 128;
    int tid = threadIdx.x;
    int warpId = tid >> 5, lane = tid & 31;
    int grp = lane >> 2, tig = lane & 3;
    int wm = warpId * 16;
    int r0 = wm + grp, r1 = wm + grp + 8;

    const float* Q0 = qh + ((size_t)h * TSEQ + t0) * HDIM;
    uint32_t qf[8][4];
#pragma unroll
    for (int ks = 0; ks < 8; ks++) {
        int kb = ks * 8;
        qf[ks][0] = __float_as_uint(Q0[r0 * HDIM + kb + tig]);
        qf[ks][1] = __float_as_uint(Q0[r1 * HDIM + kb + tig]);
        qf[ks][2] = __float_as_uint(Q0[r0 * HDIM + kb + tig + 4]);
        qf[ks][3] = __float_as_uint(Q0[r1 * HDIM + kb + tig + 4]);
    }

    float rowM0 = -INFINITY, rowM1 = -INFINITY;
    float rowL0 = 0.f, rowL1 = 0.f;

    float oacc[8][4];
#pragma unroll
    for (int ni = 0; ni < 8; ni++)
#pragma unroll
        for (int q = 0; q < 4; q++) oacc[ni][q] = 0.f;

    const float* Kb = kh + (size_t)h * TSEQ * HDIM;
    const float* Vb = vh + (size_t)h * TSEQ * HDIM;

    int ktMax = 2 * qt + 1;
    for (int kt = 0; kt <= ktMax; kt++) {
        __syncthreads();
        for (int i = tid; i < 1024; i += 256) {
            int row = i >> 4, c4 = (i & 15) * 4;
            *(float4*)&Ks[row][c4] = *(const float4*)(Kb + (size_t)(kt * 64 + row) * HDIM + c4);
            *(float4*)&Vs[row][c4] = *(const float4*)(Vb + (size_t)(kt * 64 + row) * HDIM + c4);
        }
        __syncthreads();

        float sacc[8][4];
#pragma unroll
        for (int ni = 0; ni < 8; ni++)
#pragma unroll
            for (int q = 0; q < 4; q++) sacc[ni][q] = 0.f;
#pragma unroll
        for (int ks = 0; ks < 8; ks++) {
            int kb = ks * 8;
#pragma unroll
            for (int ni = 0; ni < 8; ni++) {
                int n = ni * 8 + grp;
                uint32_t bf[2];
                bf[0] = __float_as_uint(Ks[n][kb + tig]);
                bf[1] = __float_as_uint(Ks[n][kb + tig + 4]);
                mma_tf32(sacc[ni], qf[ks], bf);
            }
        }

        unsigned int mw0[2], mw1[2];
        mw0[0] = mask[(t0 + r0) * 64 + kt * 2];
        mw0[1] = mask[(t0 + r0) * 64 + kt * 2 + 1];
        mw1[0] = mask[(t0 + r1) * 64 + kt * 2];
        mw1[1] = mask[(t0 + r1) * 64 + kt * 2 + 1];
#pragma unroll
        for (int ni = 0; ni < 8; ni++) {
            int c = ni * 8 + tig * 2;
            int wsel = c >> 5, b = c & 31;
            sacc[ni][0] = ((mw0[wsel] >> b) & 1u)       ? sacc[ni][0] * 0.125f : -INFINITY;
            sacc[ni][1] = ((mw0[wsel] >> (b + 1)) & 1u) ? sacc[ni][1] * 0.125f : -INFINITY;
            sacc[ni][2] = ((mw1[wsel] >> b) & 1u)       ? sacc[ni][2] * 0.125f : -INFINITY;
            sacc[ni][3] = ((mw1[wsel] >> (b + 1)) & 1u) ? sacc[ni][3] * 0.125f : -INFINITY;
        }

        float tmax0 = -INFINITY, tmax1 = -INFINITY;
#pragma unroll
        for (int ni = 0; ni < 8; ni++) {
            tmax0 = fmaxf(tmax0, fmaxf(sacc[ni][0], sacc[ni][1]));
            tmax1 = fmaxf(tmax1, fmaxf(sacc[ni][2], sacc[ni][3]));
        }
        tmax0 = fmaxf(tmax0, __shfl_xor_sync(0xFFFFFFFFu, tmax0, 1));
        tmax0 = fmaxf(tmax0, __shfl_xor_sync(0xFFFFFFFFu, tmax0, 2));
        tmax1 = fmaxf(tmax1, __shfl_xor_sync(0xFFFFFFFFu, tmax1, 1));
        tmax1 = fmaxf(tmax1, __shfl_xor_sync(0xFFFFFFFFu, tmax1, 2));

        float mnew0 = fmaxf(rowM0, tmax0), mnew1 = fmaxf(rowM1, tmax1);
        bool inval0 = (mnew0 == -INFINITY), inval1 = (mnew1 == -INFINITY);

        float tsum0 = 0.f, tsum1 = 0.f;
#pragma unroll
        for (int ni = 0; ni < 8; ni++) {
            int c = ni * 8 + tig * 2;
            float p00 = inval0 ? 0.f : expf(sacc[ni][0] - mnew0);
            float p01 = inval0 ? 0.f : expf(sacc[ni][1] - mnew0);
            float p10 = inval1 ? 0.f : expf(sacc[ni][2] - mnew1);
            float p11 = inval1 ? 0.f : expf(sacc[ni][3] - mnew1);
            Ps[r0][c]     = rtf(p00);
            Ps[r0][c + 1] = rtf(p01);
            Ps[r1][c]     = rtf(p10);
            Ps[r1][c + 1] = rtf(p11);
            tsum0 += p00; tsum0 += p01;
            tsum1 += p10; tsum1 += p11;
        }
        tsum0 += __shfl_xor_sync(0xFFFFFFFFu, tsum0, 1);
        tsum0 += __shfl_xor_sync(0xFFFFFFFFu, tsum0, 2);
        tsum1 += __shfl_xor_sync(0xFFFFFFFFu, tsum1, 1);
        tsum1 += __shfl_xor_sync(0xFFFFFFFFu, tsum1, 2);

        float sc0 = inval0 ? 1.f : expf(rowM0 - mnew0);
        float sc1 = inval1 ? 1.f : expf(rowM1 - mnew1);
        rowM0 = mnew0; rowM1 = mnew1;
        rowL0 = rowL0 * sc0 + tsum0;
        rowL1 = rowL1 * sc1 + tsum1;

#pragma unroll
        for (int ni = 0; ni < 8; ni++) {
            oacc[ni][0] *= sc0; oacc[ni][1] *= sc0;
            oacc[ni][2] *= sc1; oacc[ni][3] *= sc1;
        }
        __syncwarp();

#pragma unroll
        for (int ks = 0; ks < 8; ks++) {
            int kb = ks * 8;
            uint32_t pa[4];
            pa[0] = __float_as_uint(Ps[r0][kb + tig]);
            pa[1] = __float_as_uint(Ps[r1][kb + tig]);
            pa[2] = __float_as_uint(Ps[r0][kb + tig + 4]);
            pa[3] = __float_as_uint(Ps[r1][kb + tig + 4]);
#pragma unroll
            for (int ni = 0; ni < 8; ni++) {
                int n = ni * 8 + grp;
                uint32_t vf[2];
                vf[0] = __float_as_uint(Vs[kb + tig][n]);
                vf[1] = __float_as_uint(Vs[kb + tig + 4][n]);
                mma_tf32(oacc[ni], pa, vf);
            }
        }
    }

    float i0 = 1.f / rowL0;
    float i1 = 1.f / rowL1;
#pragma unroll
    for (int ni = 0; ni < 8; ni++) {
        int c = ni * 8 + tig * 2;
        size_t o0 = (size_t)(t0 + r0) * DMODEL + h * HDIM + c;
        size_t o1 = (size_t)(t0 + r1) * DMODEL + h * HDIM + c;
        av[o0]     = rtf(oacc[ni][0] * i0);
        av[o0 + 1] = rtf(oacc[ni][1] * i0);
        av[o1]     = rtf(oacc[ni][2] * i1);
        av[o1 + 1] = rtf(oacc[ni][3] * i1);
    }
}

// ---------------- fused rmsnorm2 + router ----------------
__global__ __launch_bounds__(256) void norm2_router_kernel(
    const float* __restrict__ x1, const float* __restrict__ norm2_w,
    const float* __restrict__ rw, const float* __restrict__ rb,
    float* __restrict__ x2n, float* __restrict__ probs,
    int* __restrict__ topE, float* __restrict__ topG)
{
    int t = blockIdx.x, tid = threadIdx.x;
    __shared__ float red[256];
    __shared__ float lg[8];
    const float* xr = x1 + (size_t)t * DMODEL;

    float s = 0.f;
    for (int d = tid; d < DMODEL; d += 256) { float v = xr[d]; s += v * v; }
    red[tid] = s; __syncthreads();
    for (int o = 128; o > 0; o >>= 1) { if (tid < o) red[tid] += red[tid + o]; __syncthreads(); }
    float rms = rsqrtf(red[0] / (float)DMODEL + 1e-6f);
    __syncthreads();

    float vloc[4];
    float* yr = x2n + (size_t)t * DMODEL;
    {
        int k = 0;
        for (int d = tid; d < DMODEL; d += 256, k++) {
            float v = xr[d] * rms * norm2_w[d];
            vloc[k] = v;
            yr[d] = rtf(v);
        }
    }

    float acc[8];
#pragma unroll
    for (int e = 0; e < 8; e++) acc[e] = 0.f;
    {
        int k = 0;
        for (int d = tid; d < DMODEL; d += 256, k++) {
            float xv = vloc[k];
#pragma unroll
            for (int e = 0; e < 8; e++) acc[e] += xv * rw[(size_t)d * NEXP + e];
        }
    }
    for (int e = 0; e < 8; e++) {
        red[tid] = acc[e]; __syncthreads();
        for (int o = 128; o > 0; o >>= 1) { if (tid < o) red[tid] += red[tid + o]; __syncthreads(); }
        if (tid == 0) lg[e] = red[0] + rb[e];
        __syncthreads();
    }
    if (tid == 0) {
        float m = lg[0];
        for (int e = 1; e < 8; e++) m = fmaxf(m, lg[e]);
        float p[8], sum = 0.f;
        for (int e = 0; e < 8; e++) { p[e] = expf(lg[e] - m); sum += p[e]; }
        for (int e = 0; e < 8; e++) p[e] /= sum;
        int e0 = 0;
        for (int e = 1; e < 8; e++) if (p[e] > p[e0]) e0 = e;
        int e1 = -1;
        for (int e = 0; e < 8; e++) if (e != e0 && (e1 < 0 || p[e] > p[e1])) e1 = e;
        float denom = p[e0] + p[e1];
        for (int e = 0; e < 8; e++) probs[(size_t)t * NEXP + e] = p[e];
        topE[t * 2 + 0] = e0; topE[t * 2 + 1] = e1;
        topG[t * 2 + 0] = p[e0] / denom; topG[t * 2 + 1] = p[e1] / denom;
    }
}

// ---------------- deterministic grouping (warp-ballot scan) ----------------
__global__ __launch_bounds__(256) void group_kernel(
    const int* __restrict__ topE, int* __restrict__ counts,
    int* __restrict__ segoff, int* __restrict__ rowmap,
    int* __restrict__ slotpos)
{
    __shared__ short sE[TSEQ * 2];
    __shared__ int sSeg[NEXP + 1];
    __shared__ int sCnt[NEXP];
    int tid = threadIdx.x;
    int lane = tid & 31, w = tid >> 5;
    for (int i = tid; i < TSEQ * 2; i += 256) sE[i] = (short)topE[i];
    __syncthreads();

    {
        int e = w;
        int c = 0;
        for (int i0 = 0; i0 < TSEQ * 2; i0 += 32) {
            unsigned int m = __ballot_sync(0xFFFFFFFFu, sE[i0 + lane] == e);
            c += __popc(m);
        }
        if (lane == 0) { counts[e] = c; sCnt[e] = c; }
    }
    __syncthreads();
    if (tid == 0) {
        int o = 0;
        for (int i = 0; i < 8; i++) { sSeg[i] = o; segoff[i] = o; o += sCnt[i]; }
        sSeg[8] = o; segoff[8] = o;
    }
    __syncthreads();

    {
        int e = w;
        int pos = sSeg[e];
        unsigned int ltmask = (1u << lane) - 1u;
        for (int i0 = 0; i0 < TSEQ * 2; i0 += 32) {
            int i = i0 + lane;
            bool match = (sE[i] == e);
            unsigned int m = __ballot_sync(0xFFFFFFFFu, match);
            if (match) {
                int off = __popc(m & ltmask);
                rowmap[pos + off] = i >> 1;
                slotpos[i] = pos + off;
            }
            pos += __popc(m);
        }
    }
}

// ---------------- fused combine | aux ----------------
__global__ __launch_bounds__(256) void combine_aux_kernel(
    const float* __restrict__ x1, const float* __restrict__ y,
    const int* __restrict__ slotpos, const float* __restrict__ topG,
    const float* __restrict__ probs, const int* __restrict__ counts,
    float* __restrict__ out, float* __restrict__ outAux)
{
    int tid = threadIdx.x;
    if (blockIdx.x < (TSEQ * DMODEL / 4) / 256) {
        int i4 = blockIdx.x * 256 + tid;
        int t = i4 >> 8, d4 = (i4 & 255) * 4;
        int p0 = slotpos[t * 2 + 0], p1 = slotpos[t * 2 + 1];
        float g0 = topG[t * 2 + 0], g1 = topG[t * 2 + 1];
        float4 a = *(const float4*)(x1 + (size_t)t * DMODEL + d4);
        float4 y0 = *(const float4*)(y + (size_t)p0 * DMODEL + d4);
        float4 y1 = *(const float4*)(y + (size_t)p1 * DMODEL + d4);
        float4 r;
        r.x = a.x + g0 * y0.x + g1 * y1.x;
        r.y = a.y + g0 * y0.y + g1 * y1.y;
        r.z = a.z + g0 * y0.z + g1 * y1.z;
        r.w = a.w + g0 * y0.w + g1 * y1.w;
        *(float4*)(out + (size_t)t * DMODEL + d4) = r;
    } else {
        __shared__ float red[256];
        float a = 0.f;
        for (int e = 0; e < 8; e++) {
            float s = 0.f;
            for (int t = tid; t < TSEQ; t += 256) s += probs[(size_t)t * NEXP + e];
            red[tid] = s; __syncthreads();
            for (int o = 128; o > 0; o >>= 1) { if (tid < o) red[tid] += red[tid + o]; __syncthreads(); }
            if (tid == 0) a += (float)counts[e] * red[0];
            __syncthreads();
        }
        if (tid == 0) *outAux = 8.f * a / ((float)TSEQ * (float)TSEQ);
    }
}

// ---------------- host launch ----------------
#define GETSYM(ptr, sym) do { void* _p_; cudaGetSymbolAddress(&_p_, sym); ptr = (decltype(ptr))_p_; } while (0)

extern "C" void kernel_launch(void* const* d_in, const int* in_sizes, int n_in,
                              void* d_out, int out_size)
{
    const float* x        = (const float*)d_in[0];
    const float* norm1_w  = (const float*)d_in[1];
    const float* norm2_w  = (const float*)d_in[2];
    const float* wq_idx   = (const float*)d_in[3];
    const float* wk_idx   = (const float*)d_in[4];
    const float* w_head   = (const float*)d_in[5];
    const float* wq       = (const float*)d_in[6];
    const float* wk       = (const float*)d_in[7];
    const float* wv       = (const float*)d_in[8];
    const float* wo       = (const float*)d_in[9];
    const float* router_w = (const float*)d_in[10];
    const float* router_b = (const float*)d_in[11];
    const float* w1       = (const float*)d_in[12];
    const float* b1       = (const float*)d_in[13];
    const float* w2       = (const float*)d_in[14];
    const float* b2       = (const float*)d_in[15];

    float* out    = (float*)d_out;
    float* auxp   = out + (size_t)TSEQ * DMODEL;
    float* idxout = auxp + 1;

    float *p_xn, *p_all, *p_qh, *p_kh, *p_vh;
    float *p_av, *p_x1, *p_x2n, *p_probs, *p_topG, *p_mid, *p_y;
    float *p_woc, *p_wall;
    int *p_topE, *p_counts, *p_segoff, *p_rowmap, *p_slotpos;
    unsigned int *p_mask;
    GETSYM(p_xn, g_xn); GETSYM(p_all, g_all);
    GETSYM(p_qh, g_qh); GETSYM(p_kh, g_kh); GETSYM(p_vh, g_vh);
    GETSYM(p_av, g_av); GETSYM(p_x1, g_x1); GETSYM(p_x2n, g_x2n);
    GETSYM(p_probs, g_probs); GETSYM(p_topE, g_topE); GETSYM(p_topG, g_topG);
    GETSYM(p_counts, g_counts); GETSYM(p_segoff, g_segoff);
    GETSYM(p_rowmap, g_rowmap); GETSYM(p_slotpos, g_slotpos);
    GETSYM(p_mid, g_mid); GETSYM(p_y, g_yy); GETSYM(p_mask, g_mask);
    GETSYM(p_woc, g_woc); GETSYM(p_wall, g_wall);

    cudaFuncSetAttribute(tgemm<0>, cudaFuncAttributeMaxDynamicSharedMemorySize, TG_SMEM_BYTES);
    cudaFuncSetAttribute(tgemm<1>, cudaFuncAttributeMaxDynamicSharedMemorySize, TG_SMEM_BYTES);

    // 1. fused prep: rmsnorm1 | pack_all | round4(wo)
    prep_kernel<<<TSEQ + PACK_BLOCKS + WO4_BLOCKS, 256>>>(
        x, norm1_w, p_xn, wq, wk, wv, wq_idx, wk_idx, w_head, p_wall, wo, p_woc);

    // 2. single fused projection GEMM (qkv + indexer, N=3396)
    tgemm<0><<<dim3((NALL + 127) / 128, 16, 1), 256, TG_SMEM_BYTES>>>(
        p_xn, DMODEL, nullptr, p_wall, 0, nullptr, 0,
        nullptr, p_all, NALL, nullptr, TSEQ, NALL, DMODEL, 0);

    // 3. fused indexer scores | rope, then top-512 mask
    idx_rope_kernel<<<1024 + (TSEQ * DMODEL) / 256, 256>>>(p_all, idxout, p_qh, p_kh, p_vh);
    topk_mask_kernel<<<TSEQ, 512>>>(idxout, p_mask);

    // 4. dense masked flash attention
    attn_flash<<<dim3(TSEQ / 128, NHEAD), 256>>>(p_qh, p_kh, p_vh, p_mask, p_av);

    // 5. output projection + residual
    tgemm<0><<<dim3(8, 16, 1), 256, TG_SMEM_BYTES>>>(p_av, DMODEL, nullptr, p_woc, 0, nullptr, 0,
        x, p_x1, DMODEL, nullptr, TSEQ, DMODEL, DMODEL, 0);

    // 6. fused norm2+router, grouping
    norm2_router_kernel<<<TSEQ, 256>>>(p_x1, norm2_w, router_w, router_b,
                                       p_x2n, p_probs, p_topE, p_topG);
    group_kernel<<<1, 256>>>(p_topE, p_counts, p_segoff, p_rowmap, p_slotpos);

    // 7. MoE grouped GEMMs (raw weights, tf32 cvt at fragment load)
    tgemm<1><<<dim3(DFFN / 128, 16, NEXP), 256, TG_SMEM_BYTES>>>(
        p_x2n, DMODEL, p_rowmap, w1, (long long)DMODEL * DFFN, b1, DFFN,
        nullptr, p_mid, DFFN, p_segoff, 0, DFFN, DMODEL, 1);
    tgemm<1><<<dim3(DMODEL / 128, 16, NEXP), 256, TG_SMEM_BYTES>>>(
        p_mid, DFFN, nullptr, w2, (long long)DFFN * DMODEL, b2, DMODEL,
        nullptr, p_y, DMODEL, p_segoff, 0, DMODEL, DFFN, 0);

    // 8. fused combine | aux
    combine_aux_kernel<<<(TSEQ * DMODEL / 4) / 256 + 1, 256>>>(
        p_x1, p_y, p_slotpos, p_topG, p_probs, p_counts, out, auxp);
}